// round 4
// baseline (speedup 1.0000x reference)
#include <cuda_runtime.h>
#include <math.h>

#define B 2
#define H 16
#define W 4000
#define PLANE (H*W)          // 64000
#define NPIX (B*PLANE)       // 128000
#define CH 64
#define CDT 80
#define NFLOW 8
#define NLAYER 8

typedef unsigned long long u64;

// ---- packed fp32x2 helpers (Blackwell FFMA2 path; exact fp32) ----
__device__ __forceinline__ u64 dup2(float x) {
    u64 r; asm("mov.b64 %0, {%1, %1};" : "=l"(r) : "f"(x)); return r;
}
__device__ __forceinline__ void ffma2(u64& d, u64 a, u64 b) {
    asm("fma.rn.f32x2 %0, %1, %2, %0;" : "+l"(d) : "l"(a), "l"(b));
}
__device__ __forceinline__ void unpk(u64 v, float& lo, float& hi) {
    asm("mov.b64 {%0, %1}, %2;" : "=f"(lo), "=f"(hi) : "l"(v));
}

// ---------------- persistent device scratch ----------------
__device__ float g_res2[2][B*CH*H*W];             // residual ping-pong
__device__ float g_skp[B*CH*H*W];                 // skip accumulator
__device__ float g_xbuf[2][NPIX];                 // x ping-pong
__device__ float g_wT [NFLOW*NLAYER*CH*9*128];    // conv weights [fl][ci][tap][co]
__device__ float g_cwT[NFLOW*NLAYER*CDT*128];     // cond weights [fl][ci][co]
__device__ float g_uwT[NFLOW*NLAYER*CH*128];      // res|skp wts  [fl][ci][o]

#define N1 (NFLOW*NLAYER*CH*9*128)
#define N2 (NFLOW*NLAYER*CDT*128)
#define N3 (NFLOW*NLAYER*CH*128)

__global__ void transpose_weights(const float* __restrict__ iw,
                                  const float* __restrict__ cw,
                                  const float* __restrict__ rw,
                                  const float* __restrict__ sw)
{
    long idx = (long)blockIdx.x * 256 + threadIdx.x;
    if (idx < N1) {
        int co  = (int)(idx & 127);
        long t  = idx >> 7;
        int tap = (int)(t % 9); t /= 9;
        int ci  = (int)(t & 63);
        int fl  = (int)(t >> 6);
        int kh = tap / 3, kw = tap % 3;
        g_wT[idx] = iw[((((long)fl*128 + co)*64 + ci)*3 + kh)*3 + kw];
    } else if (idx < N1 + N2) {
        long i2 = idx - N1;
        int co = (int)(i2 & 127);
        long t = i2 >> 7;
        int ci = (int)(t % CDT);
        int fl = (int)(t / CDT);
        g_cwT[i2] = cw[((long)fl*128 + co)*CDT + ci];
    } else if (idx < N1 + N2 + N3) {
        long i3 = idx - N1 - N2;
        int o  = (int)(i3 & 127);
        long t = i3 >> 7;
        int ci = (int)(t & 63);
        int fl = (int)(t >> 6);
        g_uwT[i3] = (o < 64) ? rw[((long)fl*64 + o)*64 + ci]
                             : sw[((long)fl*64 + (o-64))*64 + ci];
    }
}

// ---------------- first causal conv (1->64) + tanh, zero skip ----------------
__global__ void __launch_bounds__(256) first_conv(const float* __restrict__ fw,
                                                  const float* __restrict__ xext,
                                                  int flow)
{
    __shared__ float fsh[128];
    if (threadIdx.x < 128) fsh[threadIdx.x] = fw[threadIdx.x];
    __syncthreads();
    int pix = blockIdx.x * 256 + threadIdx.x;
    if (pix >= NPIX) return;
    int b = pix / PLANE;
    int rem = pix - b * PLANE;
    int h = rem / W;
    int w = rem - h * W;
    const float* xs = (flow == 0) ? xext : g_xbuf[(flow + 1) & 1];
    float x2 = (h >= 2) ? xs[pix - 2*W] : 0.f;
    float x1 = (h >= 1) ? xs[pix - W]   : 0.f;
    #pragma unroll 4
    for (int o = 0; o < 64; o++) {
        float v = tanhf(fsh[2*o] * x2 + fsh[2*o + 1] * x1);
        int idx = ((b*64 + o)*H + h)*W + w;
        g_res2[0][idx] = v;
        g_skp[idx] = 0.f;
    }
}

// ---------------- fused dilated gated conv + cond + res/skip update ----------------
// tile: 64 pixels x 128 g-channels. thread = 4 px (wsub) x 2 co-pairs x {T,S} (og).
// reads res from g_res2[rb], writes updated res to g_res2[rb^1] (no cross-block race).
template<int D>
__global__ void __launch_bounds__(256, 2) conv_gate(const float* __restrict__ cin,
                                                    int flow, int fl, int rb)
{
    extern __shared__ float sh[];
    float* res_sh = sh;            // 3*64*80 = 15360 floats
    float* w_sh   = sh + 15360;    // 10240 floats (conv chunk / cond / update weights)
    float* act_sh = sh;            // reuse of res_sh r=0 area: 64ch x 64px = 4096 floats

    const int tid  = threadIdx.x;
    const int wsub = tid & 15;
    const int og   = tid >> 4;
    const int bh = blockIdx.y;
    const int b = bh >> 4, h = bh & 15;
    const int w0 = blockIdx.x * 64;

    const float* rin  = g_res2[rb];
    float*       rout = g_res2[rb ^ 1];
    const float* wT  = g_wT  + (long)fl * (CH*9*128);
    const float* cwT = g_cwT + (long)fl * (CDT*128);

    // load res tile: 3 tap rows (h-2D, h-D, h) x 64 ci x [w0-8, w0+72)
    for (int idx = tid; idx < 3*64*80; idx += 256) {
        int wl = idx % 80;
        int t  = idx / 80;
        int ci = t & 63;
        int r  = t >> 6;
        int hs = h - (2 - r) * D;
        int wg = w0 + wl - 8;
        float v = 0.f;
        if (hs >= 0 && (unsigned)wg < (unsigned)W)
            v = rin[((b*64 + ci)*H + hs)*W + wg];
        res_sh[idx] = v;
    }

    u64 aT[2][4], aS[2][4];          // [co-pair][px], packed fp32x2
    #pragma unroll
    for (int j = 0; j < 2; j++)
        #pragma unroll
        for (int p = 0; p < 4; p++) { aT[j][p] = 0ull; aS[j][p] = 0ull; }

    // main conv: chunks of 8 input channels; weights staged to shared
    for (int cb = 0; cb < 64; cb += 8) {
        __syncthreads();
        {
            const float4* wsrc = (const float4*)(wT + (long)cb * 9 * 128);
            float4* wdst = (float4*)w_sh;
            #pragma unroll
            for (int i = 0; i < 9; i++) wdst[tid + i*256] = wsrc[tid + i*256];
        }
        __syncthreads();
        #pragma unroll 2
        for (int cc = 0; cc < 8; cc++) {
            const int ci = cb + cc;
            const float* wrow = w_sh + cc * (9*128);
            #pragma unroll
            for (int r = 0; r < 3; r++) {
                const float* rp = res_sh + (r*64 + ci)*80 + (wsub << 2);
                float4 winv[5];
                float* win = (float*)winv;
                if (D == 8) {
                    #pragma unroll
                    for (int jj = 0; jj < 5; jj++)
                        winv[jj] = *(const float4*)(rp + 4*jj);
                } else {
                    #pragma unroll
                    for (int jj = 1; jj <= 3; jj++)
                        winv[jj] = *(const float4*)(rp + 4*jj);
                }
                #pragma unroll
                for (int kw = 0; kw < 3; kw++) {
                    ulonglong2 wt2 = *(const ulonglong2*)(wrow + (r*3+kw)*128 + (og << 2));
                    ulonglong2 ws2 = *(const ulonglong2*)(wrow + (r*3+kw)*128 + (og << 2) + 64);
                    #pragma unroll
                    for (int p = 0; p < 4; p++) {
                        u64 xx = dup2(win[8 + p + (kw-1)*D]);
                        ffma2(aT[0][p], wt2.x, xx);
                        ffma2(aT[1][p], wt2.y, xx);
                        ffma2(aS[0][p], ws2.x, xx);
                        ffma2(aS[1][p], ws2.y, xx);
                    }
                }
            }
        }
    }

    // conditioner: g += cwT[ci] * c[b,ci,hm,w]  (flip map composed analytically)
    __syncthreads();
    {
        const float4* csrc = (const float4*)cwT;
        float4* cdst = (float4*)w_sh;
        #pragma unroll
        for (int i = 0; i < 10; i++) cdst[tid + i*256] = csrc[tid + i*256];
    }
    __syncthreads();

    int hm = h;
    #pragma unroll 1
    for (int j = flow - 1; j >= 0; j--)
        hm = (j < 4) ? (15 - hm) : (hm < 8 ? 7 - hm : 23 - hm);

    const int wpix = w0 + (wsub << 2);
    const bool inb = wpix < W;   // W%4==0 so float4 fully in or out
    #pragma unroll 4
    for (int ci = 0; ci < CDT; ci++) {
        float4 cv = inb ? *(const float4*)(cin + ((long)(b*CDT + ci)*H + hm)*W + wpix)
                        : make_float4(0.f, 0.f, 0.f, 0.f);
        float cvc[4] = {cv.x, cv.y, cv.z, cv.w};
        ulonglong2 wt2 = *(const ulonglong2*)(w_sh + ci*128 + (og << 2));
        ulonglong2 ws2 = *(const ulonglong2*)(w_sh + ci*128 + (og << 2) + 64);
        #pragma unroll
        for (int p = 0; p < 4; p++) {
            u64 xx = dup2(cvc[p]);
            ffma2(aT[0][p], wt2.x, xx);
            ffma2(aT[1][p], wt2.y, xx);
            ffma2(aS[0][p], ws2.x, xx);
            ffma2(aS[1][p], ws2.y, xx);
        }
    }

    // act = tanh(g_t) * sigmoid(g_s) -> stage to shared (act_sh overlays res_sh r=0)
    {
        float t0, t1, s0, s1;
        #pragma unroll
        for (int j = 0; j < 4; j++) {
            float av[4];
            #pragma unroll
            for (int p = 0; p < 4; p++) {
                unpk(aT[j >> 1][p], t0, t1);
                unpk(aS[j >> 1][p], s0, s1);
                float tv = (j & 1) ? t1 : t0;
                float sv = (j & 1) ? s1 : s0;
                av[p] = tanhf(tv) * (1.f / (1.f + expf(-sv)));
            }
            int co = (og << 2) + j;
            *(float4*)(act_sh + co*64 + (wsub << 2)) = make_float4(av[0], av[1], av[2], av[3]);
        }
    }
    __syncthreads();

    // stage update weights [64ci x 128o] into w_sh
    {
        const float4* usrc = (const float4*)(g_uwT + (long)fl * (CH*128));
        float4* udst = (float4*)w_sh;
        #pragma unroll
        for (int i = 0; i < 8; i++) udst[tid + i*256] = usrc[tid + i*256];
    }
    __syncthreads();

    // update: res_out = res_in + rw@act ; skp += sw@act
    u64 aR[2][4], aK[2][4];
    #pragma unroll
    for (int j = 0; j < 2; j++)
        #pragma unroll
        for (int p = 0; p < 4; p++) { aR[j][p] = 0ull; aK[j][p] = 0ull; }

    #pragma unroll 4
    for (int ci = 0; ci < 64; ci++) {
        float4 av = *(const float4*)(act_sh + ci*64 + (wsub << 2));
        float avc[4] = {av.x, av.y, av.z, av.w};
        ulonglong2 wr2 = *(const ulonglong2*)(w_sh + ci*128 + (og << 2));
        ulonglong2 wk2 = *(const ulonglong2*)(w_sh + ci*128 + (og << 2) + 64);
        #pragma unroll
        for (int p = 0; p < 4; p++) {
            u64 xx = dup2(avc[p]);
            ffma2(aR[0][p], wr2.x, xx);
            ffma2(aR[1][p], wr2.y, xx);
            ffma2(aK[0][p], wk2.x, xx);
            ffma2(aK[1][p], wk2.y, xx);
        }
    }

    if (inb) {
        float lo, hi;
        #pragma unroll
        for (int j = 0; j < 4; j++) {
            int o = (og << 2) + j;
            // center row of res_in lives in res_sh r=2 (offset 10240.., untouched by act_sh)
            float4 cr = *(const float4*)(res_sh + (2*64 + o)*80 + 8 + (wsub << 2));
            float4 rv, kv;
            float rr[4], kk[4];
            #pragma unroll
            for (int p = 0; p < 4; p++) {
                unpk(aR[j >> 1][p], lo, hi);
                rr[p] = (j & 1) ? hi : lo;
                unpk(aK[j >> 1][p], lo, hi);
                kk[p] = (j & 1) ? hi : lo;
            }
            rv = make_float4(cr.x + rr[0], cr.y + rr[1], cr.z + rr[2], cr.w + rr[3]);
            long idx = ((long)(b*64 + o)*H + h)*W + wpix;
            *(float4*)(rout + idx) = rv;
            float4 s = *(float4*)(g_skp + idx);
            kv = make_float4(s.x + kk[0], s.y + kk[1], s.z + kk[2], s.w + kk[3]);
            *(float4*)(g_skp + idx) = kv;
        }
    }
}

// ---------------- post: relu->p1->relu->p2, mean/logvar, gm/gl/x update, flip ----------------
__global__ void __launch_bounds__(256) post_kernel(const float* __restrict__ p1,
                                                   const float* __restrict__ p2,
                                                   const float* __restrict__ xext,
                                                   float* __restrict__ out,
                                                   int flow)
{
    __shared__ float p1T[64*64];
    __shared__ float p2s[128];
    for (int i = threadIdx.x; i < 4096; i += 256) {
        int k = i >> 6, j = i & 63;
        p1T[j*64 + k] = p1[i];          // p1T[j][k] = p1[k][j]
    }
    if (threadIdx.x < 128) p2s[threadIdx.x] = p2[threadIdx.x];
    __syncthreads();

    int pix = blockIdx.x * 256 + threadIdx.x;
    if (pix >= NPIX) return;
    int b = pix / PLANE;
    int rem = pix - b * PLANE;
    int h = rem / W;
    int w = rem - h * W;

    u64 h2[32];
    #pragma unroll
    for (int k = 0; k < 32; k++) h2[k] = 0ull;

    for (int j = 0; j < 64; j++) {
        float s = g_skp[((b*64 + j)*H + h)*W + w];
        s = fmaxf(s, 0.f);
        u64 ss = dup2(s);
        const ulonglong2* prow = (const ulonglong2*)(p1T + j*64);
        #pragma unroll
        for (int k2 = 0; k2 < 16; k2++) {
            ulonglong2 wv = prow[k2];
            ffma2(h2[2*k2],     wv.x, ss);
            ffma2(h2[2*k2 + 1], wv.y, ss);
        }
    }
    float o0 = 0.f, o1 = 0.f;
    #pragma unroll
    for (int k = 0; k < 32; k++) {
        float lo, hi;
        unpk(h2[k], lo, hi);
        float h0 = fmaxf(lo, 0.f);
        float h1v = fmaxf(hi, 0.f);
        o0 = fmaf(p2s[2*k], h0, o0);     o0 = fmaf(p2s[2*k+1], h1v, o0);
        o1 = fmaf(p2s[64 + 2*k], h0, o1); o1 = fmaf(p2s[64 + 2*k+1], h1v, o1);
    }
    float mean = o0;
    float lv = fminf(o1, 10.f);
    float e = expf(lv);

    float* gm = out + NPIX;
    float* gl = out + 2*NPIX;
    if (flow == 0) { gm[pix] = mean; gl[pix] = lv; }
    else           { gm[pix] = gm[pix]*e + mean; gl[pix] += lv; }

    const float* xs = (flow == 0) ? xext : g_xbuf[(flow + 1) & 1];
    float xn = e * xs[pix] + mean;
    int hd = (flow < 4) ? (15 - h) : (h < 8 ? 7 - h : 23 - h);
    int odx = b*PLANE + hd*W + w;
    g_xbuf[flow & 1][odx] = xn;
    if (flow == NFLOW - 1) out[odx] = xn;
}

// ---------------- host launcher ----------------
extern "C" void kernel_launch(void* const* d_in, const int* in_sizes, int n_in,
                              void* d_out, int out_size)
{
    const float* x       = (const float*)d_in[0];
    const float* c       = (const float*)d_in[1];
    const float* first_w = (const float*)d_in[2];
    const float* init_w  = (const float*)d_in[3];
    const float* cdt_w   = (const float*)d_in[4];
    const float* res_w   = (const float*)d_in[5];
    const float* skp_w   = (const float*)d_in[6];
    const float* p1      = (const float*)d_in[7];
    const float* p2      = (const float*)d_in[8];
    float* out = (float*)d_out;

    const int CONV_SMEM = (15360 + 10240) * 4;   // 102400 bytes
    cudaFuncSetAttribute(conv_gate<1>, cudaFuncAttributeMaxDynamicSharedMemorySize, CONV_SMEM);
    cudaFuncSetAttribute(conv_gate<2>, cudaFuncAttributeMaxDynamicSharedMemorySize, CONV_SMEM);
    cudaFuncSetAttribute(conv_gate<4>, cudaFuncAttributeMaxDynamicSharedMemorySize, CONV_SMEM);
    cudaFuncSetAttribute(conv_gate<8>, cudaFuncAttributeMaxDynamicSharedMemorySize, CONV_SMEM);

    transpose_weights<<<(N1 + N2 + N3) / 256, 256>>>(init_w, cdt_w, res_w, skp_w);

    dim3 gconv((W + 63) / 64, B * H);   // (63, 32)

    for (int f = 0; f < NFLOW; f++) {
        first_conv<<<(NPIX + 255) / 256, 256>>>(first_w + f * 128, x, f);
        for (int l = 0; l < NLAYER; l++) {
            int d = 1 << (l & 3);
            int fl = f * NLAYER + l;
            int rb = l & 1;
            switch (d) {
                case 1: conv_gate<1><<<gconv, 256, CONV_SMEM>>>(c, f, fl, rb); break;
                case 2: conv_gate<2><<<gconv, 256, CONV_SMEM>>>(c, f, fl, rb); break;
                case 4: conv_gate<4><<<gconv, 256, CONV_SMEM>>>(c, f, fl, rb); break;
                default: conv_gate<8><<<gconv, 256, CONV_SMEM>>>(c, f, fl, rb); break;
            }
        }
        post_kernel<<<(NPIX + 255) / 256, 256>>>(p1 + f * 64 * 64, p2 + f * 2 * 64, x, out, f);
    }
    (void)in_sizes; (void)n_in; (void)out_size;
}

// round 8
// speedup vs baseline: 1.3758x; 1.3758x over previous
#include <cuda_runtime.h>
#include <math.h>
#include <stdint.h>

#define B 2
#define H 16
#define W 4000
#define PLANE (H*W)
#define NPIX (B*PLANE)
#define CDT 80
#define NFLOW 8
#define NLAYER 8
typedef unsigned long long u64;
typedef unsigned int u32;

// strides / smem layout (floats)
#define SA 152          // res tile row stride (144 used)
#define SB 132          // weight tile row stride (128 used)
#define SC 136          // c / g / act / d2 row stride (128 used)
#define WS_OFF 29184    // 3*64*SA
#define WSLOT 10560     // 80*SB
#define SMEMF (WS_OFF + 2*WSLOT)   // 50304 floats = 201216 B

// ---------------- helpers ----------------
__device__ __forceinline__ u32 smem_u32(const void* p) {
    u32 a; asm("{ .reg .u64 t; cvta.to.shared.u64 t, %1; cvt.u32.u64 %0, t; }" : "=r"(a) : "l"(p));
    return a;
}
__device__ __forceinline__ float tf32r(float x) {
    u32 r; asm("cvt.rna.tf32.f32 %0, %1;" : "=r"(r) : "f"(x));
    return __uint_as_float(r);
}
__device__ __forceinline__ u64 dup2(float x) { u64 r; asm("mov.b64 %0, {%1, %1};" : "=l"(r) : "f"(x)); return r; }
__device__ __forceinline__ void ffma2(u64& d, u64 a, u64 b) { asm("fma.rn.f32x2 %0, %1, %2, %0;" : "+l"(d) : "l"(a), "l"(b)); }
__device__ __forceinline__ void unpk(u64 v, float& lo, float& hi) { asm("mov.b64 {%0, %1}, %2;" : "=f"(lo), "=f"(hi) : "l"(v)); }

#define CPA16(d, s) asm volatile("cp.async.cg.shared.global [%0], [%1], 16;" :: "r"(d), "l"(s) : "memory")
#define CP_COMMIT() asm volatile("cp.async.commit_group;" ::: "memory")
#define CP_WAIT1()  asm volatile("cp.async.wait_group 1;" ::: "memory")
#define CP_WAIT0()  asm volatile("cp.async.wait_group 0;" ::: "memory")

__device__ __forceinline__ void mma8(float* d, const u32* a, u32 b0, u32 b1) {
    asm("mma.sync.aligned.m16n8k8.row.col.f32.tf32.tf32.f32 "
        "{%0,%1,%2,%3}, {%4,%5,%6,%7}, {%8,%9}, {%0,%1,%2,%3};"
        : "+f"(d[0]), "+f"(d[1]), "+f"(d[2]), "+f"(d[3])
        : "r"(a[0]), "r"(a[1]), "r"(a[2]), "r"(a[3]), "r"(b0), "r"(b1));
}

// one k8 chunk for a 64x32 warp tile: A stored [k][m] in smem, B stored [k][n]
__device__ __forceinline__ void gemm_k8(float (&acc)[4][4][4],
    const float* As, int sa, const float* Bs, int k0, int pm, int pn, int gid, int tg)
{
    u32 a[4][4];
    const float* ar = As + (k0 + tg) * sa;
    #pragma unroll
    for (int ms = 0; ms < 4; ms++) {
        const float* ap = ar + pm + ms*16 + gid;
        a[ms][0] = __float_as_uint(ap[0]);
        a[ms][1] = __float_as_uint(ap[8]);
        a[ms][2] = __float_as_uint(ap[4*sa]);
        a[ms][3] = __float_as_uint(ap[4*sa + 8]);
    }
    const float* br = Bs + (k0 + tg) * SB + pn + gid;
    #pragma unroll
    for (int ns = 0; ns < 4; ns++) {
        u32 b0 = __float_as_uint(br[ns*8]);
        u32 b1 = __float_as_uint(br[ns*8 + 4*SB]);
        #pragma unroll
        for (int ms = 0; ms < 4; ms++) mma8(acc[ms][ns], a[ms], b0, b1);
    }
}

// ---------------- persistent scratch ----------------
__device__ __align__(16) float g_res2[2][B*64*PLANE];
__device__ __align__(16) float g_skp[B*64*PLANE];
__device__ __align__(16) float g_xbuf[2][NPIX];
__device__ __align__(16) float g_wT [NFLOW*NLAYER*64*9*128];  // [fl][ci][tap][co], tf32-rounded
__device__ __align__(16) float g_cwT[NFLOW*NLAYER*CDT*128];   // [fl][ci][co]
__device__ __align__(16) float g_uwT[NFLOW*NLAYER*64*128];    // [fl][ci][o]

#define N1 (NFLOW*NLAYER*64*9*128)
#define N2 (NFLOW*NLAYER*CDT*128)
#define N3 (NFLOW*NLAYER*64*128)

__global__ void prep_weights(const float* __restrict__ iw, const float* __restrict__ cw,
                             const float* __restrict__ rw, const float* __restrict__ sw)
{
    long idx = (long)blockIdx.x * 256 + threadIdx.x;
    if (idx < N1) {
        int co  = (int)(idx & 127);
        long t  = idx >> 7;
        int tap = (int)(t % 9); t /= 9;
        int ci  = (int)(t & 63);
        int fl  = (int)(t >> 6);
        int kh = tap / 3, kw = tap % 3;
        g_wT[idx] = tf32r(iw[((((long)fl*128 + co)*64 + ci)*3 + kh)*3 + kw]);
    } else if (idx < N1 + N2) {
        long i2 = idx - N1;
        int co = (int)(i2 & 127);
        long t = i2 >> 7;
        int ci = (int)(t % CDT);
        int fl = (int)(t / CDT);
        g_cwT[i2] = tf32r(cw[((long)fl*128 + co)*CDT + ci]);
    } else if (idx < N1 + N2 + N3) {
        long i3 = idx - N1 - N2;
        int o  = (int)(i3 & 127);
        long t = i3 >> 7;
        int ci = (int)(t & 63);
        int fl = (int)(t >> 6);
        g_uwT[i3] = tf32r((o < 64) ? rw[((long)fl*64 + o)*64 + ci]
                                   : sw[((long)fl*64 + (o-64))*64 + ci]);
    }
}

// ---------------- first conv ----------------
__global__ void __launch_bounds__(256) first_conv(const float* __restrict__ fw,
                                                  const float* __restrict__ xext, int flow)
{
    __shared__ float fsh[128];
    if (threadIdx.x < 128) fsh[threadIdx.x] = fw[threadIdx.x];
    __syncthreads();
    int pix = blockIdx.x * 256 + threadIdx.x;
    if (pix >= NPIX) return;
    int b = pix / PLANE, rem = pix - b * PLANE, h = rem / W, w = rem - (rem / W) * W;
    const float* xs = (flow == 0) ? xext : g_xbuf[(flow + 1) & 1];
    float x2 = (h >= 2) ? xs[pix - 2*W] : 0.f;
    float x1 = (h >= 1) ? xs[pix - W]   : 0.f;
    #pragma unroll 4
    for (int o = 0; o < 64; o++) {
        float v = tanhf(fsh[2*o]*x2 + fsh[2*o+1]*x1);
        int idx = ((b*64 + o)*H + h)*W + w;
        g_res2[0][idx] = v; g_skp[idx] = 0.f;
    }
}

// ---------------- fused layer: warp-MMA tf32 ----------------
template<int D>
__global__ void __launch_bounds__(256) layer_kernel(const float* __restrict__ cin,
                                                    int flow, int fl, int rb)
{
    extern __shared__ __align__(16) float sh[];
    const int tid = threadIdx.x, lane = tid & 31, wq = tid >> 5;
    const int b = blockIdx.y >> 4, h = blockIdx.y & 15;
    const int w0 = blockIdx.x * 128;
    const int pm = (wq & 1) * 64, pn = (wq >> 1) * 32;
    const int gid = lane >> 2, tg = lane & 3;
    const float* rin = g_res2[rb];
    float* rout = g_res2[rb ^ 1];
    const u32 shb = smem_u32(sh);

    // stage res halo tile: 3 tap rows x 64 ci x 144 px, tf32-rounded
    for (int idx = tid; idx < 3*64*144; idx += 256) {
        int px = idx % 144;
        int t = idx / 144;
        int ci = t & 63, r = t >> 6;
        int hs = h - (2 - r) * D;
        int wg = w0 + px - 8;
        float v = (hs >= 0 && (unsigned)wg < (unsigned)W)
                ? rin[((b*64 + ci)*H + hs)*W + wg] : 0.f;
        sh[(r*64 + ci)*SA + px] = tf32r(v);
    }

    const float* wsrc[11];
    #pragma unroll
    for (int s = 0; s < 9; s++) wsrc[s] = g_wT + (long)fl*73728 + s*128;
    wsrc[9]  = g_cwT + (long)fl*10240;
    wsrc[10] = g_uwT + (long)fl*8192;

    int hm = h;
    #pragma unroll 1
    for (int j = flow - 1; j >= 0; j--)
        hm = (j < 4) ? (15 - hm) : (hm < 8 ? 7 - hm : 23 - hm);

    auto stage = [&](int i) {
        int nq = (i == 9) ? 2560 : 2048;       // rows*32 16B-chunks
        int sstr = (i < 9) ? 1152 : 128;       // src row stride (floats)
        const float* src = wsrc[i];
        u32 dstb = shb + (u32)(WS_OFF + (i & 1)*WSLOT) * 4;
        for (int q = tid; q < nq; q += 256) {
            int ci = q >> 5, jj = q & 31;
            CPA16(dstb + (u32)(ci*SB + jj*4)*4, src + ci*sstr + jj*4);
        }
        CP_COMMIT();
    };

    float acc[4][4][4];
    #pragma unroll
    for (int ms = 0; ms < 4; ms++)
        #pragma unroll
        for (int ns = 0; ns < 4; ns++)
            #pragma unroll
            for (int q = 0; q < 4; q++) acc[ms][ns][q] = 0.f;

    stage(0);
    for (int i = 0; i <= 9; i++) {
        stage(i + 1);
        CP_WAIT1();
        __syncthreads();
        const float* Bs = sh + WS_OFF + (i & 1)*WSLOT;
        if (i < 9) {
            int r = i / 3, kw = i - 3*r;
            const float* As = sh + r*64*SA + (kw - 1)*D + 8;
            #pragma unroll 2
            for (int kc = 0; kc < 8; kc++) gemm_k8(acc, As, SA, Bs, kc*8, pm, pn, gid, tg);
        } else {
            #pragma unroll 2
            for (int kc = 0; kc < 10; kc++) gemm_k8(acc, sh, SC, Bs, kc*8, pm, pn, gid, tg);
        }
        __syncthreads();
        if (i == 8) {
            // stage conditioner activations (overwrites tap-A rows; taps done)
            for (int idx = tid; idx < 80*128; idx += 256) {
                int px = idx & 127, ci = idx >> 7;
                int wg = w0 + px;
                float v = (wg < W) ? cin[((long)(b*CDT + ci)*H + hm)*W + wg] : 0.f;
                sh[ci*SC + px] = tf32r(v);
            }
            __syncthreads();
        }
    }

    // scatter g to smem [co][px], reset acc
    #pragma unroll
    for (int ms = 0; ms < 4; ms++)
        #pragma unroll
        for (int ns = 0; ns < 4; ns++) {
            int px0 = pm + ms*16 + gid, co0 = pn + ns*8 + tg*2;
            sh[co0*SC + px0]         = acc[ms][ns][0];
            sh[(co0+1)*SC + px0]     = acc[ms][ns][1];
            sh[co0*SC + px0 + 8]     = acc[ms][ns][2];
            sh[(co0+1)*SC + px0 + 8] = acc[ms][ns][3];
            acc[ms][ns][0] = acc[ms][ns][1] = acc[ms][ns][2] = acc[ms][ns][3] = 0.f;
        }
    __syncthreads();
    // gate: act[ci][px] = tanh(g[ci]) * sigmoid(g[ci+64]), rows 0..63 in place
    for (int e = tid; e < 64*128; e += 256) {
        int ci = e >> 7, px = e & 127;
        float t = sh[ci*SC + px], s = sh[(ci + 64)*SC + px];
        sh[ci*SC + px] = tf32r(tanhf(t) * (1.f / (1.f + expf(-s))));
    }
    CP_WAIT0();
    __syncthreads();

    // update GEMM: D2[px][o] = act @ [rw|sw]  (slot 0 holds update weights)
    {
        const float* Bs = sh + WS_OFF;
        #pragma unroll 2
        for (int kc = 0; kc < 8; kc++) gemm_k8(acc, sh, SC, Bs, kc*8, pm, pn, gid, tg);
    }
    __syncthreads();
    // scatter D2 into ws region [o][px]
    float* d2 = sh + WS_OFF;
    #pragma unroll
    for (int ms = 0; ms < 4; ms++)
        #pragma unroll
        for (int ns = 0; ns < 4; ns++) {
            int px0 = pm + ms*16 + gid, co0 = pn + ns*8 + tg*2;
            d2[co0*SC + px0]         = acc[ms][ns][0];
            d2[(co0+1)*SC + px0]     = acc[ms][ns][1];
            d2[co0*SC + px0 + 8]     = acc[ms][ns][2];
            d2[(co0+1)*SC + px0 + 8] = acc[ms][ns][3];
        }
    __syncthreads();

    // coalesced writeout: thread -> (o, 64-px half)
    {
        int co = tid >> 1;
        int ph = (tid & 1) * 64;
        int ch = co & 63;
        long gb = ((long)(b*64 + ch)*H + h)*W + w0 + ph;
        const float4* dp = (const float4*)(d2 + co*SC + ph);
        if (co < 64) {
            #pragma unroll 4
            for (int j = 0; j < 16; j++) {
                if (w0 + ph + j*4 < W) {
                    float4 rv = *(const float4*)(rin + gb + j*4);
                    float4 dv = dp[j];
                    rv.x += dv.x; rv.y += dv.y; rv.z += dv.z; rv.w += dv.w;
                    *(float4*)(rout + gb + j*4) = rv;
                }
            }
        } else {
            #pragma unroll 4
            for (int j = 0; j < 16; j++) {
                if (w0 + ph + j*4 < W) {
                    float4 sv = *(const float4*)(g_skp + gb + j*4);
                    float4 dv = dp[j];
                    sv.x += dv.x; sv.y += dv.y; sv.z += dv.z; sv.w += dv.w;
                    *(float4*)(g_skp + gb + j*4) = sv;
                }
            }
        }
    }
}

// ---------------- post ----------------
__global__ void __launch_bounds__(256) post_kernel(const float* __restrict__ p1,
                                                   const float* __restrict__ p2,
                                                   const float* __restrict__ xext,
                                                   float* __restrict__ out, int flow)
{
    __shared__ float p1T[64*64];
    __shared__ float p2s[128];
    for (int i = threadIdx.x; i < 4096; i += 256) p1T[(i & 63)*64 + (i >> 6)] = p1[i];
    if (threadIdx.x < 128) p2s[threadIdx.x] = p2[threadIdx.x];
    __syncthreads();
    int pix = blockIdx.x * 256 + threadIdx.x;
    if (pix >= NPIX) return;
    int b = pix / PLANE, rem = pix - b * PLANE, h = rem / W, w = rem - (rem / W) * W;

    u64 h2[32];
    #pragma unroll
    for (int k = 0; k < 32; k++) h2[k] = 0ull;
    for (int j = 0; j < 64; j++) {
        float s = fmaxf(g_skp[((b*64 + j)*H + h)*W + w], 0.f);
        u64 ss = dup2(s);
        const ulonglong2* pr = (const ulonglong2*)(p1T + j*64);
        #pragma unroll
        for (int k2 = 0; k2 < 16; k2++) {
            ulonglong2 wv2 = pr[k2];
            ffma2(h2[2*k2], wv2.x, ss);
            ffma2(h2[2*k2+1], wv2.y, ss);
        }
    }
    float o0 = 0.f, o1 = 0.f;
    #pragma unroll
    for (int k = 0; k < 32; k++) {
        float lo, hi; unpk(h2[k], lo, hi);
        float a = fmaxf(lo, 0.f), bb = fmaxf(hi, 0.f);
        o0 = fmaf(p2s[2*k], a, o0);      o0 = fmaf(p2s[2*k+1], bb, o0);
        o1 = fmaf(p2s[64+2*k], a, o1);   o1 = fmaf(p2s[64+2*k+1], bb, o1);
    }
    float mean = o0, lv = fminf(o1, 10.f), e = expf(lv);
    float* gm = out + NPIX; float* gl = out + 2*NPIX;
    if (flow == 0) { gm[pix] = mean; gl[pix] = lv; }
    else           { gm[pix] = gm[pix]*e + mean; gl[pix] += lv; }
    const float* xs = (flow == 0) ? xext : g_xbuf[(flow + 1) & 1];
    float xn = e * xs[pix] + mean;
    int hd = (flow < 4) ? (15 - h) : (h < 8 ? 7 - h : 23 - h);
    int odx = b*PLANE + hd*W + w;
    g_xbuf[flow & 1][odx] = xn;
    if (flow == NFLOW - 1) out[odx] = xn;
}

// ---------------- host ----------------
extern "C" void kernel_launch(void* const* d_in, const int* in_sizes, int n_in,
                              void* d_out, int out_size)
{
    const float* x       = (const float*)d_in[0];
    const float* c       = (const float*)d_in[1];
    const float* first_w = (const float*)d_in[2];
    const float* init_w  = (const float*)d_in[3];
    const float* cdt_w   = (const float*)d_in[4];
    const float* res_w   = (const float*)d_in[5];
    const float* skp_w   = (const float*)d_in[6];
    const float* p1      = (const float*)d_in[7];
    const float* p2      = (const float*)d_in[8];
    float* out = (float*)d_out;

    const int SMEMB = SMEMF * 4;   // 201216
    cudaFuncSetAttribute(layer_kernel<1>, cudaFuncAttributeMaxDynamicSharedMemorySize, SMEMB);
    cudaFuncSetAttribute(layer_kernel<2>, cudaFuncAttributeMaxDynamicSharedMemorySize, SMEMB);
    cudaFuncSetAttribute(layer_kernel<4>, cudaFuncAttributeMaxDynamicSharedMemorySize, SMEMB);
    cudaFuncSetAttribute(layer_kernel<8>, cudaFuncAttributeMaxDynamicSharedMemorySize, SMEMB);

    long tot = (long)N1 + N2 + N3;
    prep_weights<<<(unsigned)((tot + 255) / 256), 256>>>(init_w, cdt_w, res_w, skp_w);

    dim3 gl((W + 127) / 128, B * H);   // (32, 32)
    for (int f = 0; f < NFLOW; f++) {
        first_conv<<<(NPIX + 255) / 256, 256>>>(first_w + f * 128, x, f);
        for (int l = 0; l < NLAYER; l++) {
            int d = 1 << (l & 3);
            int fl = f * NLAYER + l;
            int rb = l & 1;
            switch (d) {
                case 1:  layer_kernel<1><<<gl, 256, SMEMB>>>(c, f, fl, rb); break;
                case 2:  layer_kernel<2><<<gl, 256, SMEMB>>>(c, f, fl, rb); break;
                case 4:  layer_kernel<4><<<gl, 256, SMEMB>>>(c, f, fl, rb); break;
                default: layer_kernel<8><<<gl, 256, SMEMB>>>(c, f, fl, rb); break;
            }
        }
        post_kernel<<<(NPIX + 255) / 256, 256>>>(p1 + f * 64 * 64, p2 + f * 2 * 64, x, out, f);
    }
    (void)in_sizes; (void)n_in; (void)out_size;
}

// round 10
// speedup vs baseline: 1.8288x; 1.3292x over previous
#include <cuda_runtime.h>
#include <math.h>
#include <stdint.h>

#define B 2
#define H 16
#define W 4000
#define PLANE (H*W)
#define NPIX (B*PLANE)
#define CDT 80
#define NFLOW 8
#define NLAYER 8
typedef unsigned long long u64;
typedef unsigned int u32;

// smem layout (floats): [R1 9728][SML 8704][BIG 8704] = 27136 floats = 108544 B
#define SA 152          // A tap-row stride (144 used) ; 152%32=24 -> conflict-free frags
#define SB 136          // weight row stride (128 used); 136%32=8  -> conflict-free frags
#define SC 136          // cond/g/act/d2 row stride (128 used)
#define R1F 0
#define SMLF 9728
#define BIGF 18432
#define SMEMF 27136

// ---------------- helpers ----------------
__device__ __forceinline__ u32 smem_u32(const void* p) {
    u32 a; asm("{ .reg .u64 t; cvta.to.shared.u64 t, %1; cvt.u32.u64 %0, t; }" : "=r"(a) : "l"(p));
    return a;
}
__device__ __forceinline__ float tf32r(float x) {
    u32 r; asm("cvt.rna.tf32.f32 %0, %1;" : "=r"(r) : "f"(x));
    return __uint_as_float(r);
}
__device__ __forceinline__ u64 dup2(float x) { u64 r; asm("mov.b64 %0, {%1, %1};" : "=l"(r) : "f"(x)); return r; }
__device__ __forceinline__ void ffma2(u64& d, u64 a, u64 b) { asm("fma.rn.f32x2 %0, %1, %2, %0;" : "+l"(d) : "l"(a), "l"(b)); }
__device__ __forceinline__ void unpk(u64 v, float& lo, float& hi) { asm("mov.b64 {%0, %1}, %2;" : "=f"(lo), "=f"(hi) : "l"(v)); }

#define CPA16(d, s) asm volatile("cp.async.cg.shared.global [%0], [%1], 16;" :: "r"(d), "l"(s) : "memory")
#define CP_COMMIT() asm volatile("cp.async.commit_group;" ::: "memory")
#define CP_WAIT1()  asm volatile("cp.async.wait_group 1;" ::: "memory")
#define CP_WAIT0()  asm volatile("cp.async.wait_group 0;" ::: "memory")

__device__ __forceinline__ void mma8(float* d, const u32* a, u32 b0, u32 b1) {
    asm("mma.sync.aligned.m16n8k8.row.col.f32.tf32.tf32.f32 "
        "{%0,%1,%2,%3}, {%4,%5,%6,%7}, {%8,%9}, {%0,%1,%2,%3};"
        : "+f"(d[0]), "+f"(d[1]), "+f"(d[2]), "+f"(d[3])
        : "r"(a[0]), "r"(a[1]), "r"(a[2]), "r"(a[3]), "r"(b0), "r"(b1));
}

// one k8 chunk for a 64x32 warp tile: A stored [k][m], B stored [k][n]
__device__ __forceinline__ void gemm_k8(float (&acc)[4][4][4],
    const float* As, int sa, const float* Bs, int k0, int pm, int pn, int gid, int tg)
{
    u32 a[4][4];
    const float* ar = As + (k0 + tg) * sa;
    #pragma unroll
    for (int ms = 0; ms < 4; ms++) {
        const float* ap = ar + pm + ms*16 + gid;
        a[ms][0] = __float_as_uint(ap[0]);
        a[ms][1] = __float_as_uint(ap[8]);
        a[ms][2] = __float_as_uint(ap[4*sa]);
        a[ms][3] = __float_as_uint(ap[4*sa + 8]);
    }
    const float* br = Bs + (k0 + tg) * SB + pn + gid;
    #pragma unroll
    for (int ns = 0; ns < 4; ns++) {
        u32 b0 = __float_as_uint(br[ns*8]);
        u32 b1 = __float_as_uint(br[ns*8 + 4*SB]);
        #pragma unroll
        for (int ms = 0; ms < 4; ms++) mma8(acc[ms][ns], a[ms], b0, b1);
    }
}

// ---------------- persistent scratch ----------------
__device__ __align__(16) float g_res2[2][B*64*PLANE];
__device__ __align__(16) float g_skp[B*64*PLANE];
__device__ __align__(16) float g_xbuf[2][NPIX];
__device__ __align__(16) float g_wT [NFLOW*NLAYER*64*9*128];  // [fl][ci][tap][co], tf32-rounded
__device__ __align__(16) float g_cwT[NFLOW*NLAYER*CDT*128];   // [fl][ci][co]
__device__ __align__(16) float g_uwT[NFLOW*NLAYER*64*128];    // [fl][ci][o]

#define N1 (NFLOW*NLAYER*64*9*128)
#define N2 (NFLOW*NLAYER*CDT*128)
#define N3 (NFLOW*NLAYER*64*128)

__global__ void prep_weights(const float* __restrict__ iw, const float* __restrict__ cw,
                             const float* __restrict__ rw, const float* __restrict__ sw)
{
    long idx = (long)blockIdx.x * 256 + threadIdx.x;
    if (idx < N1) {
        int co  = (int)(idx & 127);
        long t  = idx >> 7;
        int tap = (int)(t % 9); t /= 9;
        int ci  = (int)(t & 63);
        int fl  = (int)(t >> 6);
        int kh = tap / 3, kw = tap % 3;
        g_wT[idx] = tf32r(iw[((((long)fl*128 + co)*64 + ci)*3 + kh)*3 + kw]);
    } else if (idx < N1 + N2) {
        long i2 = idx - N1;
        int co = (int)(i2 & 127);
        long t = i2 >> 7;
        int ci = (int)(t % CDT);
        int fl = (int)(t / CDT);
        g_cwT[i2] = tf32r(cw[((long)fl*128 + co)*CDT + ci]);
    } else if (idx < N1 + N2 + N3) {
        long i3 = idx - N1 - N2;
        int o  = (int)(i3 & 127);
        long t = i3 >> 7;
        int ci = (int)(t & 63);
        int fl = (int)(t >> 6);
        g_uwT[i3] = tf32r((o < 64) ? rw[((long)fl*64 + o)*64 + ci]
                                   : sw[((long)fl*64 + (o-64))*64 + ci]);
    }
}

// ---------------- first conv ----------------
__global__ void __launch_bounds__(256) first_conv(const float* __restrict__ fw,
                                                  const float* __restrict__ xext, int flow)
{
    __shared__ float fsh[128];
    if (threadIdx.x < 128) fsh[threadIdx.x] = fw[threadIdx.x];
    __syncthreads();
    int pix = blockIdx.x * 256 + threadIdx.x;
    if (pix >= NPIX) return;
    int b = pix / PLANE, rem = pix - b * PLANE, h = rem / W, w = rem - (rem / W) * W;
    const float* xs = (flow == 0) ? xext : g_xbuf[(flow + 1) & 1];
    float x2 = (h >= 2) ? xs[pix - 2*W] : 0.f;
    float x1 = (h >= 1) ? xs[pix - W]   : 0.f;
    #pragma unroll 4
    for (int o = 0; o < 64; o++) {
        float v = tanhf(fsh[2*o]*x2 + fsh[2*o+1]*x1);
        int idx = ((b*64 + o)*H + h)*W + w;
        g_res2[0][idx] = v; g_skp[idx] = 0.f;
    }
}

// ---------------- fused layer: warp-MMA tf32, 2 CTAs/SM ----------------
template<int D>
__global__ void __launch_bounds__(256, 2) layer_kernel(const float* __restrict__ cin,
                                                       int flow, int fl, int rb)
{
    extern __shared__ __align__(16) float sh[];
    const int tid = threadIdx.x, lane = tid & 31, wq = tid >> 5;
    const int b = blockIdx.y >> 4, h = blockIdx.y & 15;
    const int w0 = blockIdx.x * 128;
    const int pm = (wq & 1) * 64, pn = (wq >> 1) * 32;
    const int gid = lane >> 2, tg = lane & 3;
    const float* rin = g_res2[rb];
    float* rout = g_res2[rb ^ 1];
    const u32 shb = smem_u32(sh);

    const float* wA = g_wT + (long)fl*73728;   // row stride 1152, tap s at +s*128
    const float* wC = g_cwT + (long)fl*10240;  // row stride 128
    const float* wU = g_uwT + (long)fl*8192;   // row stride 128

    int hm = h;
    #pragma unroll 1
    for (int j = flow - 1; j >= 0; j--)
        hm = (j < 4) ? (15 - hm) : (hm < 8 ? 7 - hm : 23 - hm);

    // stage `rows`x128 weight rows into slot (16B chunks), one commit group
    auto stage_w = [&](u32 dst_off, const float* src, int sstr, int rows) {
        u32 dstb = shb + dst_off * 4;
        int nq = rows * 32;
        for (int q = tid; q < nq; q += 256) {
            int ci = q >> 5, jj = q & 31;
            CPA16(dstb + (u32)(ci*SB + jj*4)*4, src + (long)ci*sstr + jj*4);
        }
        CP_COMMIT();
    };
    auto slot = [&](int i) -> u32 { return (i & 1) ? BIGF : SMLF; };

    float acc[4][4][4];
    #pragma unroll
    for (int ms = 0; ms < 4; ms++)
        #pragma unroll
        for (int ns = 0; ns < 4; ns++)
            #pragma unroll
            for (int q = 0; q < 4; q++) acc[ms][ns][q] = 0.f;

    stage_w(SMLF, wA + 0*128, 1152, 64);   // tap 0

    // -------- conv taps: stage one h-row of res at a time --------
    for (int r = 0; r < 3; r++) {
        // stage A row r: 64 ci x 144 px (tf32)
        {
            int hs = h - (2 - r) * D;
            for (int idx = tid; idx < 64*144; idx += 256) {
                int px = idx % 144, ci = idx / 144;
                int wg = w0 + px - 8;
                float v = (hs >= 0 && (unsigned)wg < (unsigned)W)
                        ? rin[((b*64 + ci)*H + hs)*W + wg] : 0.f;
                sh[ci*SA + px] = tf32r(v);
            }
        }
        #pragma unroll 1
        for (int kw = 0; kw < 3; kw++) {
            int i = 3*r + kw;
            if (i < 8)      stage_w(slot(i+1), wA + (i+1)*128, 1152, 64);
            else            stage_w(BIGF, wC, 128, 40);          // cond W half 1
            CP_WAIT1();
            __syncthreads();
            const float* As = sh + (kw - 1)*D + 8;
            const float* Bs = sh + slot(i);
            #pragma unroll 2
            for (int kc = 0; kc < 8; kc++) gemm_k8(acc, As, SA, Bs, kc*8, pm, pn, gid, tg);
            __syncthreads();
        }
    }

    // -------- conditioner (K=80) in two 40-row halves --------
    // acts half 1 -> R1
    for (int idx = tid; idx < 40*128; idx += 256) {
        int px = idx & 127, ci = idx >> 7;
        int wg = w0 + px;
        float v = (wg < W) ? cin[((long)(b*CDT + ci)*H + hm)*W + wg] : 0.f;
        sh[ci*SC + px] = tf32r(v);
    }
    stage_w(SMLF, wC + 40*128, 128, 40);   // cond W half 2
    CP_WAIT1();
    __syncthreads();
    #pragma unroll 1
    for (int kc = 0; kc < 5; kc++) gemm_k8(acc, sh, SC, sh + BIGF, kc*8, pm, pn, gid, tg);
    __syncthreads();
    // acts half 2 -> R1 (rows 40..79 stored as 0..39)
    for (int idx = tid; idx < 40*128; idx += 256) {
        int px = idx & 127, ci = idx >> 7;
        int wg = w0 + px;
        float v = (wg < W) ? cin[((long)(b*CDT + ci + 40)*H + hm)*W + wg] : 0.f;
        sh[ci*SC + px] = tf32r(v);
    }
    CP_WAIT0();
    __syncthreads();
    #pragma unroll 1
    for (int kc = 5; kc < 10; kc++) gemm_k8(acc, sh, SC, sh + SMLF, kc*8 - 40, pm, pn, gid, tg);
    __syncthreads();

    // -------- scatter g [co][px] into R1+SML, reset acc --------
    #pragma unroll
    for (int ms = 0; ms < 4; ms++)
        #pragma unroll
        for (int ns = 0; ns < 4; ns++) {
            int px0 = pm + ms*16 + gid, co0 = pn + ns*8 + tg*2;
            sh[co0*SC + px0]         = acc[ms][ns][0];
            sh[(co0+1)*SC + px0]     = acc[ms][ns][1];
            sh[co0*SC + px0 + 8]     = acc[ms][ns][2];
            sh[(co0+1)*SC + px0 + 8] = acc[ms][ns][3];
            acc[ms][ns][0] = acc[ms][ns][1] = acc[ms][ns][2] = acc[ms][ns][3] = 0.f;
        }
    __syncthreads();
    // gate: act rows 0..63 in place (act fits entirely in R1)
    for (int e = tid; e < 64*128; e += 256) {
        int ci = e >> 7, px = e & 127;
        float t = sh[ci*SC + px], s = sh[(ci + 64)*SC + px];
        sh[ci*SC + px] = tf32r(tanhf(t) * (1.f / (1.f + expf(-s))));
    }
    stage_w(BIGF, wU, 128, 64);            // update weights (BIG free after cond)
    CP_WAIT0();
    __syncthreads();

    // -------- update GEMM: D2[px][o] = act @ [rw|sw] --------
    #pragma unroll 2
    for (int kc = 0; kc < 8; kc++) gemm_k8(acc, sh, SC, sh + BIGF, kc*8, pm, pn, gid, tg);
    __syncthreads();
    // scatter D2 -> SML+BIG region
    float* d2 = sh + SMLF;
    #pragma unroll
    for (int ms = 0; ms < 4; ms++)
        #pragma unroll
        for (int ns = 0; ns < 4; ns++) {
            int px0 = pm + ms*16 + gid, co0 = pn + ns*8 + tg*2;
            d2[co0*SC + px0]         = acc[ms][ns][0];
            d2[(co0+1)*SC + px0]     = acc[ms][ns][1];
            d2[co0*SC + px0 + 8]     = acc[ms][ns][2];
            d2[(co0+1)*SC + px0 + 8] = acc[ms][ns][3];
        }
    __syncthreads();

    // coalesced writeout: thread -> (o, 64-px half)
    {
        int co = tid >> 1;
        int ph = (tid & 1) * 64;
        int ch = co & 63;
        long gb = ((long)(b*64 + ch)*H + h)*W + w0 + ph;
        const float4* dp = (const float4*)(d2 + co*SC + ph);
        if (co < 64) {
            #pragma unroll 4
            for (int j = 0; j < 16; j++) {
                if (w0 + ph + j*4 < W) {
                    float4 rv = *(const float4*)(rin + gb + j*4);
                    float4 dv = dp[j];
                    rv.x += dv.x; rv.y += dv.y; rv.z += dv.z; rv.w += dv.w;
                    *(float4*)(rout + gb + j*4) = rv;
                }
            }
        } else {
            #pragma unroll 4
            for (int j = 0; j < 16; j++) {
                if (w0 + ph + j*4 < W) {
                    float4 sv = *(const float4*)(g_skp + gb + j*4);
                    float4 dv = dp[j];
                    sv.x += dv.x; sv.y += dv.y; sv.z += dv.z; sv.w += dv.w;
                    *(float4*)(g_skp + gb + j*4) = sv;
                }
            }
        }
    }
}

// ---------------- post ----------------
__global__ void __launch_bounds__(256) post_kernel(const float* __restrict__ p1,
                                                   const float* __restrict__ p2,
                                                   const float* __restrict__ xext,
                                                   float* __restrict__ out, int flow)
{
    __shared__ float p1T[64*64];
    __shared__ float p2s[128];
    for (int i = threadIdx.x; i < 4096; i += 256) p1T[(i & 63)*64 + (i >> 6)] = p1[i];
    if (threadIdx.x < 128) p2s[threadIdx.x] = p2[threadIdx.x];
    __syncthreads();
    int pix = blockIdx.x * 256 + threadIdx.x;
    if (pix >= NPIX) return;
    int b = pix / PLANE, rem = pix - b * PLANE, h = rem / W, w = rem - (rem / W) * W;

    u64 h2[32];
    #pragma unroll
    for (int k = 0; k < 32; k++) h2[k] = 0ull;
    for (int j = 0; j < 64; j++) {
        float s = fmaxf(g_skp[((b*64 + j)*H + h)*W + w], 0.f);
        u64 ss = dup2(s);
        const ulonglong2* pr = (const ulonglong2*)(p1T + j*64);
        #pragma unroll
        for (int k2 = 0; k2 < 16; k2++) {
            ulonglong2 wv2 = pr[k2];
            ffma2(h2[2*k2], wv2.x, ss);
            ffma2(h2[2*k2+1], wv2.y, ss);
        }
    }
    float o0 = 0.f, o1 = 0.f;
    #pragma unroll
    for (int k = 0; k < 32; k++) {
        float lo, hi; unpk(h2[k], lo, hi);
        float a = fmaxf(lo, 0.f), bb = fmaxf(hi, 0.f);
        o0 = fmaf(p2s[2*k], a, o0);      o0 = fmaf(p2s[2*k+1], bb, o0);
        o1 = fmaf(p2s[64+2*k], a, o1);   o1 = fmaf(p2s[64+2*k+1], bb, o1);
    }
    float mean = o0, lv = fminf(o1, 10.f), e = expf(lv);
    float* gm = out + NPIX; float* gl = out + 2*NPIX;
    if (flow == 0) { gm[pix] = mean; gl[pix] = lv; }
    else           { gm[pix] = gm[pix]*e + mean; gl[pix] += lv; }
    const float* xs = (flow == 0) ? xext : g_xbuf[(flow + 1) & 1];
    float xn = e * xs[pix] + mean;
    int hd = (flow < 4) ? (15 - h) : (h < 8 ? 7 - h : 23 - h);
    int odx = b*PLANE + hd*W + w;
    g_xbuf[flow & 1][odx] = xn;
    if (flow == NFLOW - 1) out[odx] = xn;
}

// ---------------- host ----------------
extern "C" void kernel_launch(void* const* d_in, const int* in_sizes, int n_in,
                              void* d_out, int out_size)
{
    const float* x       = (const float*)d_in[0];
    const float* c       = (const float*)d_in[1];
    const float* first_w = (const float*)d_in[2];
    const float* init_w  = (const float*)d_in[3];
    const float* cdt_w   = (const float*)d_in[4];
    const float* res_w   = (const float*)d_in[5];
    const float* skp_w   = (const float*)d_in[6];
    const float* p1      = (const float*)d_in[7];
    const float* p2      = (const float*)d_in[8];
    float* out = (float*)d_out;

    const int SMEMB = SMEMF * 4;   // 108544 B -> 2 CTAs/SM
    cudaFuncSetAttribute(layer_kernel<1>, cudaFuncAttributeMaxDynamicSharedMemorySize, SMEMB);
    cudaFuncSetAttribute(layer_kernel<2>, cudaFuncAttributeMaxDynamicSharedMemorySize, SMEMB);
    cudaFuncSetAttribute(layer_kernel<4>, cudaFuncAttributeMaxDynamicSharedMemorySize, SMEMB);
    cudaFuncSetAttribute(layer_kernel<8>, cudaFuncAttributeMaxDynamicSharedMemorySize, SMEMB);

    long tot = (long)N1 + N2 + N3;
    prep_weights<<<(unsigned)((tot + 255) / 256), 256>>>(init_w, cdt_w, res_w, skp_w);

    dim3 gl((W + 127) / 128, B * H);   // (32, 32)
    for (int f = 0; f < NFLOW; f++) {
        first_conv<<<(NPIX + 255) / 256, 256>>>(first_w + f * 128, x, f);
        for (int l = 0; l < NLAYER; l++) {
            int d = 1 << (l & 3);
            int fl = f * NLAYER + l;
            int rb = l & 1;
            switch (d) {
                case 1:  layer_kernel<1><<<gl, 256, SMEMB>>>(c, f, fl, rb); break;
                case 2:  layer_kernel<2><<<gl, 256, SMEMB>>>(c, f, fl, rb); break;
                case 4:  layer_kernel<4><<<gl, 256, SMEMB>>>(c, f, fl, rb); break;
                default: layer_kernel<8><<<gl, 256, SMEMB>>>(c, f, fl, rb); break;
            }
        }
        post_kernel<<<(NPIX + 255) / 256, 256>>>(p1 + f * 64 * 64, p2 + f * 2 * 64, x, out, f);
    }
    (void)in_sizes; (void)n_in; (void)out_size;
}

// round 13
// speedup vs baseline: 2.4708x; 1.3510x over previous
#include <cuda_runtime.h>
#include <math.h>
#include <stdint.h>

#define B 2
#define H 16
#define W 4000
#define PLANE (H*W)
#define NPIX (B*PLANE)
#define CDT 80
#define NFLOW 8
#define NLAYER 8
typedef unsigned long long u64;
typedef unsigned int u32;

// smem layout (floats): [R1 9728][SML 8704][BIG 8704] = 27136 floats = 108544 B
#define SA 152          // A tap-row stride (144 used)
#define SB 136          // weight row stride (128 used)
#define SC 136          // cond/g/act/d2 row stride (128 used)
#define SMLF 9728
#define BIGF 18432
#define SMEMF 27136

// ---------------- helpers ----------------
__device__ __forceinline__ u32 smem_u32(const void* p) {
    u32 a; asm("{ .reg .u64 t; cvta.to.shared.u64 t, %1; cvt.u32.u64 %0, t; }" : "=r"(a) : "l"(p));
    return a;
}
__device__ __forceinline__ float tf32r(float x) {
    u32 r; asm("cvt.rna.tf32.f32 %0, %1;" : "=r"(r) : "f"(x));
    return __uint_as_float(r);
}
__device__ __forceinline__ u64 dup2(float x) { u64 r; asm("mov.b64 %0, {%1, %1};" : "=l"(r) : "f"(x)); return r; }
__device__ __forceinline__ void ffma2(u64& d, u64 a, u64 b) { asm("fma.rn.f32x2 %0, %1, %2, %0;" : "+l"(d) : "l"(a), "l"(b)); }
__device__ __forceinline__ void unpk(u64 v, float& lo, float& hi) { asm("mov.b64 {%0, %1}, %2;" : "=f"(lo), "=f"(hi) : "l"(v)); }

#define CPA16(d, s)     asm volatile("cp.async.cg.shared.global [%0], [%1], 16;" :: "r"(d), "l"(s) : "memory")
#define CPA16Z(d, s, z) asm volatile("cp.async.cg.shared.global [%0], [%1], 16, %2;" :: "r"(d), "l"(s), "r"(z) : "memory")
#define CP_COMMIT() asm volatile("cp.async.commit_group;" ::: "memory")
#define CP_WAIT1()  asm volatile("cp.async.wait_group 1;" ::: "memory")
#define CP_WAIT0()  asm volatile("cp.async.wait_group 0;" ::: "memory")

__device__ __forceinline__ void mma8(float* d, const u32* a, u32 b0, u32 b1) {
    asm("mma.sync.aligned.m16n8k8.row.col.f32.tf32.tf32.f32 "
        "{%0,%1,%2,%3}, {%4,%5,%6,%7}, {%8,%9}, {%0,%1,%2,%3};"
        : "+f"(d[0]), "+f"(d[1]), "+f"(d[2]), "+f"(d[3])
        : "r"(a[0]), "r"(a[1]), "r"(a[2]), "r"(a[3]), "r"(b0), "r"(b1));
}

// one k8 chunk for a 64x32 warp tile: A stored [k][m], B stored [k][n]
__device__ __forceinline__ void gemm_k8(float (&acc)[4][4][4],
    const float* As, int sa, const float* Bs, int k0, int pm, int pn, int gid, int tg)
{
    u32 a[4][4];
    const float* ar = As + (k0 + tg) * sa;
    #pragma unroll
    for (int ms = 0; ms < 4; ms++) {
        const float* ap = ar + pm + ms*16 + gid;
        a[ms][0] = __float_as_uint(ap[0]);
        a[ms][1] = __float_as_uint(ap[8]);
        a[ms][2] = __float_as_uint(ap[4*sa]);
        a[ms][3] = __float_as_uint(ap[4*sa + 8]);
    }
    const float* br = Bs + (k0 + tg) * SB + pn + gid;
    #pragma unroll
    for (int ns = 0; ns < 4; ns++) {
        u32 b0 = __float_as_uint(br[ns*8]);
        u32 b1 = __float_as_uint(br[ns*8 + 4*SB]);
        #pragma unroll
        for (int ms = 0; ms < 4; ms++) mma8(acc[ms][ns], a[ms], b0, b1);
    }
}

// ---------------- persistent scratch ----------------
__device__ __align__(16) float g_res2[2][B*64*PLANE];   // fp32 residual (recurrence)
__device__ __align__(16) float g_resT[2][B*64*PLANE];   // tf32-rounded shadow (MMA A source)
__device__ __align__(16) float g_skp[B*64*PLANE];
__device__ __align__(16) float g_xbuf[2][NPIX];
__device__ __align__(16) float g_cT [B*CDT*PLANE];      // tf32-rounded conditioner
__device__ __align__(16) float g_wT [NFLOW*NLAYER*64*9*128];
__device__ __align__(16) float g_cwT[NFLOW*NLAYER*CDT*128];
__device__ __align__(16) float g_uwT[NFLOW*NLAYER*64*128];

#define N1 (NFLOW*NLAYER*64*9*128)
#define N2 (NFLOW*NLAYER*CDT*128)
#define N3 (NFLOW*NLAYER*64*128)
#define NC (B*CDT*PLANE)

__global__ void prep_weights(const float* __restrict__ iw, const float* __restrict__ cw,
                             const float* __restrict__ rw, const float* __restrict__ sw,
                             const float* __restrict__ cfull)
{
    long idx = (long)blockIdx.x * 256 + threadIdx.x;
    if (idx < N1) {
        int co  = (int)(idx & 127);
        long t  = idx >> 7;
        int tap = (int)(t % 9); t /= 9;
        int ci  = (int)(t & 63);
        int fl  = (int)(t >> 6);
        int kh = tap / 3, kw = tap % 3;
        g_wT[idx] = tf32r(iw[((((long)fl*128 + co)*64 + ci)*3 + kh)*3 + kw]);
    } else if (idx < N1 + N2) {
        long i2 = idx - N1;
        int co = (int)(i2 & 127);
        long t = i2 >> 7;
        int ci = (int)(t % CDT);
        int fl = (int)(t / CDT);
        g_cwT[i2] = tf32r(cw[((long)fl*128 + co)*CDT + ci]);
    } else if (idx < N1 + N2 + N3) {
        long i3 = idx - N1 - N2;
        int o  = (int)(i3 & 127);
        long t = i3 >> 7;
        int ci = (int)(t & 63);
        int fl = (int)(t >> 6);
        g_uwT[i3] = tf32r((o < 64) ? rw[((long)fl*64 + o)*64 + ci]
                                   : sw[((long)fl*64 + (o-64))*64 + ci]);
    } else if (idx < N1 + N2 + N3 + NC) {
        long i4 = idx - N1 - N2 - N3;
        g_cT[i4] = tf32r(cfull[i4]);
    }
}

// ---------------- first conv ----------------
__global__ void __launch_bounds__(256) first_conv(const float* __restrict__ fw,
                                                  const float* __restrict__ xext, int flow)
{
    __shared__ float fsh[128];
    if (threadIdx.x < 128) fsh[threadIdx.x] = fw[threadIdx.x];
    __syncthreads();
    int pix = blockIdx.x * 256 + threadIdx.x;
    if (pix >= NPIX) return;
    int b = pix / PLANE, rem = pix - b * PLANE, h = rem / W, w = rem - (rem / W) * W;
    const float* xs = (flow == 0) ? xext : g_xbuf[(flow + 1) & 1];
    float x2 = (h >= 2) ? xs[pix - 2*W] : 0.f;
    float x1 = (h >= 1) ? xs[pix - W]   : 0.f;
    #pragma unroll 4
    for (int o = 0; o < 64; o++) {
        float v = tanhf(fsh[2*o]*x2 + fsh[2*o+1]*x1);
        int idx = ((b*64 + o)*H + h)*W + w;
        g_res2[0][idx] = v;
        g_resT[0][idx] = tf32r(v);
        g_skp[idx] = 0.f;
    }
}

// ---------------- fused layer: warp-MMA tf32, all-cp.async staging ----------------
template<int D>
__global__ void __launch_bounds__(256, 2) layer_kernel(int flow, int fl, int rb)
{
    extern __shared__ __align__(16) float sh[];
    const int tid = threadIdx.x, lane = tid & 31, wq = tid >> 5;
    const int b = blockIdx.y >> 4, h = blockIdx.y & 15;
    const int w0 = blockIdx.x * 128;
    const int pm = (wq & 1) * 64, pn = (wq >> 1) * 32;
    const int gid = lane >> 2, tg = lane & 3;
    const float* rin  = g_res2[rb];
    const float* rinT = g_resT[rb];
    float* rout  = g_res2[rb ^ 1];
    float* routT = g_resT[rb ^ 1];
    const u32 shb = smem_u32(sh);

    const float* wA = g_wT + (long)fl*73728;
    const float* wC = g_cwT + (long)fl*10240;
    const float* wU = g_uwT + (long)fl*8192;

    int hm = h;
    #pragma unroll 1
    for (int j = flow - 1; j >= 0; j--)
        hm = (j < 4) ? (15 - hm) : (hm < 8 ? 7 - hm : 23 - hm);

    // ---- staging helpers (each = one commit group) ----
    auto stage_w = [&](u32 dst_off, const float* src, int sstr, int rows) {
        u32 dstb = shb + dst_off * 4;
        int nq = rows * 32;
        for (int q = tid; q < nq; q += 256) {
            int ci = q >> 5, jj = q & 31;
            CPA16(dstb + (u32)(ci*SB + jj*4)*4, src + (long)ci*sstr + jj*4);
        }
        CP_COMMIT();
    };
    // A tap-row: 64 ci x 144 px from g_resT (zero-fill halo/OOB)
    auto stage_A = [&](int hs) {
        #pragma unroll 3
        for (int q = tid; q < 2304; q += 256) {
            int ci = q / 36, j = q - (q / 36) * 36;
            int wg = w0 + j*4 - 8;
            bool ok = (hs >= 0) && ((unsigned)wg < (unsigned)W);
            const float* src = rinT + ((long)(b*64 + ci)*H + (ok ? hs : 0))*W + (ok ? wg : 0);
            u32 z = ok ? 16u : 0u;
            CPA16Z(shb + (u32)(ci*SA + j*4)*4, src, z);
        }
        CP_COMMIT();
    };
    // cond acts: 40 rows (ci0..ci0+39) x 128 px from g_cT
    auto stage_acts = [&](int ci0) {
        #pragma unroll 3
        for (int q = tid; q < 1280; q += 256) {
            int ci = q >> 5, j = q & 31;
            int wg = w0 + j*4;
            bool ok = wg < W;
            const float* src = g_cT + ((long)(b*CDT + ci0 + ci)*H + hm)*W + (ok ? wg : 0);
            u32 z = ok ? 16u : 0u;
            CPA16Z(shb + (u32)(ci*SC + j*4)*4, src, z);
        }
        CP_COMMIT();
    };
    auto slot = [&](int i) -> u32 { return (i & 1) ? BIGF : SMLF; };

    float acc[4][4][4];
    #pragma unroll
    for (int ms = 0; ms < 4; ms++)
        #pragma unroll
        for (int ns = 0; ns < 4; ns++)
            #pragma unroll
            for (int q = 0; q < 4; q++) acc[ms][ns][q] = 0.f;

    stage_A(h - 2*D);                       // pend: {A0}
    stage_w(SMLF, wA + 0*128, 1152, 64);    // pend: {A0,W0}

    // -------- 9 conv taps --------
    for (int r = 0; r < 3; r++) {
        #pragma unroll 1
        for (int kw = 0; kw < 3; kw++) {
            int i = 3*r + kw;
            if (i < 8)  stage_w(slot(i+1), wA + (i+1)*128, 1152, 64);
            else        stage_w(BIGF, wC, 128, 40);          // cond W half 1
            CP_WAIT1();                 // A-row + W_i arrived (newest stage may pend)
            __syncthreads();
            const float* As = sh + (kw - 1)*D + 8;
            const float* Bs = sh + slot(i);
            #pragma unroll 2
            for (int kc = 0; kc < 8; kc++) gemm_k8(acc, As, SA, Bs, kc*8, pm, pn, gid, tg);
            __syncthreads();
        }
        if (r < 2) stage_A(h - (1 - r)*D);   // next tap row (buffer free after sync)
    }

    // -------- conditioner (K=80), two 40-row halves --------
    stage_acts(0);                           // pend: {C1, Act1}
    stage_w(SMLF, wC + 40*128, 128, 40);     // pend: {C1, Act1, C2}
    CP_WAIT1();                              // C1 + Act1 ready
    __syncthreads();
    #pragma unroll 1
    for (int kc = 0; kc < 5; kc++) gemm_k8(acc, sh, SC, sh + BIGF, kc*8, pm, pn, gid, tg);
    __syncthreads();
    stage_acts(40);                          // pend: {C2, Act2}
    stage_w(BIGF, wU, 128, 64);              // update W (BIG free) -> {C2, Act2, U}
    CP_WAIT1();                              // C2 + Act2 ready
    __syncthreads();
    #pragma unroll 1
    for (int kc = 5; kc < 10; kc++) gemm_k8(acc, sh, SC, sh + SMLF, kc*8 - 40, pm, pn, gid, tg);
    __syncthreads();

    // -------- scatter g [co][px] into R1+SML, reset acc --------
    #pragma unroll
    for (int ms = 0; ms < 4; ms++)
        #pragma unroll
        for (int ns = 0; ns < 4; ns++) {
            int px0 = pm + ms*16 + gid, co0 = pn + ns*8 + tg*2;
            sh[co0*SC + px0]         = acc[ms][ns][0];
            sh[(co0+1)*SC + px0]     = acc[ms][ns][1];
            sh[co0*SC + px0 + 8]     = acc[ms][ns][2];
            sh[(co0+1)*SC + px0 + 8] = acc[ms][ns][3];
            acc[ms][ns][0] = acc[ms][ns][1] = acc[ms][ns][2] = acc[ms][ns][3] = 0.f;
        }
    __syncthreads();
    // gate: act rows 0..63 in place
    for (int e = tid; e < 64*128; e += 256) {
        int ci = e >> 7, px = e & 127;
        float t = sh[ci*SC + px], s = sh[(ci + 64)*SC + px];
        sh[ci*SC + px] = tf32r(tanhf(t) * (1.f / (1.f + expf(-s))));
    }
    CP_WAIT0();                              // update weights arrived
    __syncthreads();

    // -------- update GEMM: D2[px][o] = act @ [rw|sw] --------
    #pragma unroll 2
    for (int kc = 0; kc < 8; kc++) gemm_k8(acc, sh, SC, sh + BIGF, kc*8, pm, pn, gid, tg);
    __syncthreads();
    float* d2 = sh + SMLF;
    #pragma unroll
    for (int ms = 0; ms < 4; ms++)
        #pragma unroll
        for (int ns = 0; ns < 4; ns++) {
            int px0 = pm + ms*16 + gid, co0 = pn + ns*8 + tg*2;
            d2[co0*SC + px0]         = acc[ms][ns][0];
            d2[(co0+1)*SC + px0]     = acc[ms][ns][1];
            d2[co0*SC + px0 + 8]     = acc[ms][ns][2];
            d2[(co0+1)*SC + px0 + 8] = acc[ms][ns][3];
        }
    __syncthreads();

    // writeout: thread -> (o, 64-px half). co<64: res (+rounded shadow), else skip.
    {
        int co = tid >> 1;
        int ph = (tid & 1) * 64;
        int ch = co & 63;
        long gb = ((long)(b*64 + ch)*H + h)*W + w0 + ph;
        const float4* dp = (const float4*)(d2 + co*SC + ph);
        if (co < 64) {
            #pragma unroll 4
            for (int j = 0; j < 16; j++) {
                if (w0 + ph + j*4 < W) {
                    float4 rv = *(const float4*)(rin + gb + j*4);
                    float4 dv = dp[j];
                    rv.x += dv.x; rv.y += dv.y; rv.z += dv.z; rv.w += dv.w;
                    *(float4*)(rout + gb + j*4) = rv;
                    float4 rt = make_float4(tf32r(rv.x), tf32r(rv.y), tf32r(rv.z), tf32r(rv.w));
                    *(float4*)(routT + gb + j*4) = rt;
                }
            }
        } else {
            #pragma unroll 4
            for (int j = 0; j < 16; j++) {
                if (w0 + ph + j*4 < W) {
                    float4 sv = *(const float4*)(g_skp + gb + j*4);
                    float4 dv = dp[j];
                    sv.x += dv.x; sv.y += dv.y; sv.z += dv.z; sv.w += dv.w;
                    *(float4*)(g_skp + gb + j*4) = sv;
                }
            }
        }
    }
}

// ---------------- post ----------------
__global__ void __launch_bounds__(256) post_kernel(const float* __restrict__ p1,
                                                   const float* __restrict__ p2,
                                                   const float* __restrict__ xext,
                                                   float* __restrict__ out, int flow)
{
    __shared__ float p1T[64*64];
    __shared__ float p2s[128];
    for (int i = threadIdx.x; i < 4096; i += 256) p1T[(i & 63)*64 + (i >> 6)] = p1[i];
    if (threadIdx.x < 128) p2s[threadIdx.x] = p2[threadIdx.x];
    __syncthreads();
    int pix = blockIdx.x * 256 + threadIdx.x;
    if (pix >= NPIX) return;
    int b = pix / PLANE, rem = pix - b * PLANE, h = rem / W, w = rem - (rem / W) * W;

    u64 h2[32];
    #pragma unroll
    for (int k = 0; k < 32; k++) h2[k] = 0ull;
    for (int j = 0; j < 64; j++) {
        float s = fmaxf(g_skp[((b*64 + j)*H + h)*W + w], 0.f);
        u64 ss = dup2(s);
        const ulonglong2* pr = (const ulonglong2*)(p1T + j*64);
        #pragma unroll
        for (int k2 = 0; k2 < 16; k2++) {
            ulonglong2 wv2 = pr[k2];
            ffma2(h2[2*k2], wv2.x, ss);
            ffma2(h2[2*k2+1], wv2.y, ss);
        }
    }
    float o0 = 0.f, o1 = 0.f;
    #pragma unroll
    for (int k = 0; k < 32; k++) {
        float lo, hi; unpk(h2[k], lo, hi);
        float a = fmaxf(lo, 0.f), bb = fmaxf(hi, 0.f);
        o0 = fmaf(p2s[2*k], a, o0);      o0 = fmaf(p2s[2*k+1], bb, o0);
        o1 = fmaf(p2s[64+2*k], a, o1);   o1 = fmaf(p2s[64+2*k+1], bb, o1);
    }
    float mean = o0, lv = fminf(o1, 10.f), e = expf(lv);
    float* gm = out + NPIX; float* gl = out + 2*NPIX;
    if (flow == 0) { gm[pix] = mean; gl[pix] = lv; }
    else           { gm[pix] = gm[pix]*e + mean; gl[pix] += lv; }
    const float* xs = (flow == 0) ? xext : g_xbuf[(flow + 1) & 1];
    float xn = e * xs[pix] + mean;
    int hd = (flow < 4) ? (15 - h) : (h < 8 ? 7 - h : 23 - h);
    int odx = b*PLANE + hd*W + w;
    g_xbuf[flow & 1][odx] = xn;
    if (flow == NFLOW - 1) out[odx] = xn;
}

// ---------------- host ----------------
extern "C" void kernel_launch(void* const* d_in, const int* in_sizes, int n_in,
                              void* d_out, int out_size)
{
    const float* x       = (const float*)d_in[0];
    const float* c       = (const float*)d_in[1];
    const float* first_w = (const float*)d_in[2];
    const float* init_w  = (const float*)d_in[3];
    const float* cdt_w   = (const float*)d_in[4];
    const float* res_w   = (const float*)d_in[5];
    const float* skp_w   = (const float*)d_in[6];
    const float* p1      = (const float*)d_in[7];
    const float* p2      = (const float*)d_in[8];
    float* out = (float*)d_out;

    const int SMEMB = SMEMF * 4;   // 108544 B -> 2 CTAs/SM
    cudaFuncSetAttribute(layer_kernel<1>, cudaFuncAttributeMaxDynamicSharedMemorySize, SMEMB);
    cudaFuncSetAttribute(layer_kernel<2>, cudaFuncAttributeMaxDynamicSharedMemorySize, SMEMB);
    cudaFuncSetAttribute(layer_kernel<4>, cudaFuncAttributeMaxDynamicSharedMemorySize, SMEMB);
    cudaFuncSetAttribute(layer_kernel<8>, cudaFuncAttributeMaxDynamicSharedMemorySize, SMEMB);

    long tot = (long)N1 + N2 + N3 + NC;
    prep_weights<<<(unsigned)((tot + 255) / 256), 256>>>(init_w, cdt_w, res_w, skp_w, c);

    dim3 gl((W + 127) / 128, B * H);   // (32, 32)
    for (int f = 0; f < NFLOW; f++) {
        first_conv<<<(NPIX + 255) / 256, 256>>>(first_w + f * 128, x, f);
        for (int l = 0; l < NLAYER; l++) {
            int d = 1 << (l & 3);
            int fl = f * NLAYER + l;
            int rb = l & 1;
            switch (d) {
                case 1:  layer_kernel<1><<<gl, 256, SMEMB>>>(f, fl, rb); break;
                case 2:  layer_kernel<2><<<gl, 256, SMEMB>>>(f, fl, rb); break;
                case 4:  layer_kernel<4><<<gl, 256, SMEMB>>>(f, fl, rb); break;
                default: layer_kernel<8><<<gl, 256, SMEMB>>>(f, fl, rb); break;
            }
        }
        post_kernel<<<(NPIX + 255) / 256, 256>>>(p1 + f * 64 * 64, p2 + f * 2 * 64, x, out, f);
    }
    (void)in_sizes; (void)n_in; (void)out_size;
}

// round 14
// speedup vs baseline: 2.6674x; 1.0796x over previous
#include <cuda_runtime.h>
#include <math.h>
#include <stdint.h>

#define B 2
#define H 16
#define W 4000
#define PLANE (H*W)
#define NPIX (B*PLANE)
#define CDT 80
#define NFLOW 8
#define NLAYER 8
typedef unsigned long long u64;
typedef unsigned int u32;

// smem layout (floats): [R1 9728][SML 8704][BIG 8704] = 27136 floats = 108544 B
#define SA 152
#define SB 136
#define SC 136
#define SMLF 9728
#define BIGF 18432
#define SMEMF 27136

// ---------------- helpers ----------------
__device__ __forceinline__ u32 smem_u32(const void* p) {
    u32 a; asm("{ .reg .u64 t; cvta.to.shared.u64 t, %1; cvt.u32.u64 %0, t; }" : "=r"(a) : "l"(p));
    return a;
}
__device__ __forceinline__ float tf32r(float x) {
    u32 r; asm("cvt.rna.tf32.f32 %0, %1;" : "=r"(r) : "f"(x));
    return __uint_as_float(r);
}
__device__ __forceinline__ u64 dup2(float x) { u64 r; asm("mov.b64 %0, {%1, %1};" : "=l"(r) : "f"(x)); return r; }
__device__ __forceinline__ void ffma2(u64& d, u64 a, u64 b) { asm("fma.rn.f32x2 %0, %1, %2, %0;" : "+l"(d) : "l"(a), "l"(b)); }
__device__ __forceinline__ void unpk(u64 v, float& lo, float& hi) { asm("mov.b64 {%0, %1}, %2;" : "=f"(lo), "=f"(hi) : "l"(v)); }

#define CPA16(d, s)     asm volatile("cp.async.cg.shared.global [%0], [%1], 16;" :: "r"(d), "l"(s) : "memory")
#define CPA16Z(d, s, z) asm volatile("cp.async.cg.shared.global [%0], [%1], 16, %2;" :: "r"(d), "l"(s), "r"(z) : "memory")
#define CP_COMMIT() asm volatile("cp.async.commit_group;" ::: "memory")
#define CP_WAIT1()  asm volatile("cp.async.wait_group 1;" ::: "memory")
#define CP_WAIT0()  asm volatile("cp.async.wait_group 0;" ::: "memory")

__device__ __forceinline__ void mma8(float* d, const u32* a, u32 b0, u32 b1) {
    asm("mma.sync.aligned.m16n8k8.row.col.f32.tf32.tf32.f32 "
        "{%0,%1,%2,%3}, {%4,%5,%6,%7}, {%8,%9}, {%0,%1,%2,%3};"
        : "+f"(d[0]), "+f"(d[1]), "+f"(d[2]), "+f"(d[3])
        : "r"(a[0]), "r"(a[1]), "r"(a[2]), "r"(a[3]), "r"(b0), "r"(b1));
}

__device__ __forceinline__ void gemm_k8(float (&acc)[4][4][4],
    const float* As, int sa, const float* Bs, int k0, int pm, int pn, int gid, int tg)
{
    u32 a[4][4];
    const float* ar = As + (k0 + tg) * sa;
    #pragma unroll
    for (int ms = 0; ms < 4; ms++) {
        const float* ap = ar + pm + ms*16 + gid;
        a[ms][0] = __float_as_uint(ap[0]);
        a[ms][1] = __float_as_uint(ap[8]);
        a[ms][2] = __float_as_uint(ap[4*sa]);
        a[ms][3] = __float_as_uint(ap[4*sa + 8]);
    }
    const float* br = Bs + (k0 + tg) * SB + pn + gid;
    #pragma unroll
    for (int ns = 0; ns < 4; ns++) {
        u32 b0 = __float_as_uint(br[ns*8]);
        u32 b1 = __float_as_uint(br[ns*8 + 4*SB]);
        #pragma unroll
        for (int ms = 0; ms < 4; ms++) mma8(acc[ms][ns], a[ms], b0, b1);
    }
}

// ---------------- persistent scratch ----------------
__device__ __align__(16) float g_res2[2][B*64*PLANE];
__device__ __align__(16) float g_resT[2][B*64*PLANE];
__device__ __align__(16) float g_skp[B*64*PLANE];
__device__ __align__(16) float g_xbuf[2][NPIX];
__device__ __align__(16) float g_cT [B*CDT*PLANE];
__device__ __align__(16) float g_wT [NFLOW*NLAYER*64*9*128];
__device__ __align__(16) float g_cwT[NFLOW*NLAYER*CDT*128];
__device__ __align__(16) float g_uwT[NFLOW*NLAYER*64*128];

#define N1 (NFLOW*NLAYER*64*9*128)
#define N2 (NFLOW*NLAYER*CDT*128)
#define N3 (NFLOW*NLAYER*64*128)
#define NC (B*CDT*PLANE)

__global__ void prep_weights(const float* __restrict__ iw, const float* __restrict__ cw,
                             const float* __restrict__ rw, const float* __restrict__ sw,
                             const float* __restrict__ cfull)
{
    long idx = (long)blockIdx.x * 256 + threadIdx.x;
    if (idx < N1) {
        int co  = (int)(idx & 127);
        long t  = idx >> 7;
        int tap = (int)(t % 9); t /= 9;
        int ci  = (int)(t & 63);
        int fl  = (int)(t >> 6);
        int kh = tap / 3, kw = tap % 3;
        g_wT[idx] = tf32r(iw[((((long)fl*128 + co)*64 + ci)*3 + kh)*3 + kw]);
    } else if (idx < N1 + N2) {
        long i2 = idx - N1;
        int co = (int)(i2 & 127);
        long t = i2 >> 7;
        int ci = (int)(t % CDT);
        int fl = (int)(t / CDT);
        g_cwT[i2] = tf32r(cw[((long)fl*128 + co)*CDT + ci]);
    } else if (idx < N1 + N2 + N3) {
        long i3 = idx - N1 - N2;
        int o  = (int)(i3 & 127);
        long t = i3 >> 7;
        int ci = (int)(t & 63);
        int fl = (int)(t >> 6);
        g_uwT[i3] = tf32r((o < 64) ? rw[((long)fl*64 + o)*64 + ci]
                                   : sw[((long)fl*64 + (o-64))*64 + ci]);
    } else if (idx < N1 + N2 + N3 + NC) {
        long i4 = idx - N1 - N2 - N3;
        g_cT[i4] = tf32r(cfull[i4]);
    }
}

// ---------------- first conv ----------------
__global__ void __launch_bounds__(256) first_conv(const float* __restrict__ fw,
                                                  const float* __restrict__ xext, int flow)
{
    __shared__ float fsh[128];
    if (threadIdx.x < 128) fsh[threadIdx.x] = fw[threadIdx.x];
    __syncthreads();
    int pix = blockIdx.x * 256 + threadIdx.x;
    if (pix >= NPIX) return;
    int b = pix / PLANE, rem = pix - b * PLANE, h = rem / W, w = rem - (rem / W) * W;
    const float* xs = (flow == 0) ? xext : g_xbuf[(flow + 1) & 1];
    float x2 = (h >= 2) ? xs[pix - 2*W] : 0.f;
    float x1 = (h >= 1) ? xs[pix - W]   : 0.f;
    #pragma unroll 4
    for (int o = 0; o < 64; o++) {
        float v = tanhf(fsh[2*o]*x2 + fsh[2*o+1]*x1);
        int idx = ((b*64 + o)*H + h)*W + w;
        g_res2[0][idx] = v;
        g_resT[0][idx] = tf32r(v);
        g_skp[idx] = 0.f;
    }
}

// ---------------- fused layer: warp-MMA tf32, zero-tap skip ----------------
template<int D>
__global__ void __launch_bounds__(256, 2) layer_kernel(int flow, int fl, int rb)
{
    extern __shared__ __align__(16) float sh[];
    const int tid = threadIdx.x, lane = tid & 31, wq = tid >> 5;
    const int b = blockIdx.y >> 4, h = blockIdx.y & 15;
    const int w0 = blockIdx.x * 128;
    const int pm = (wq & 1) * 64, pn = (wq >> 1) * 32;
    const int gid = lane >> 2, tg = lane & 3;
    const float* rin  = g_res2[rb];
    const float* rinT = g_resT[rb];
    float* rout  = g_res2[rb ^ 1];
    float* routT = g_resT[rb ^ 1];
    const u32 shb = smem_u32(sh);

    const float* wA = g_wT + (long)fl*73728;
    const float* wC = g_cwT + (long)fl*10240;
    const float* wU = g_uwT + (long)fl*8192;

    int hm = h;
    #pragma unroll 1
    for (int j = flow - 1; j >= 0; j--)
        hm = (j < 4) ? (15 - hm) : (hm < 8 ? 7 - hm : 23 - hm);

    auto stage_w = [&](u32 dst_off, const float* src, int sstr, int rows) {
        u32 dstb = shb + dst_off * 4;
        int nq = rows * 32;
        for (int q = tid; q < nq; q += 256) {
            int ci = q >> 5, jj = q & 31;
            CPA16(dstb + (u32)(ci*SB + jj*4)*4, src + (long)ci*sstr + jj*4);
        }
        CP_COMMIT();
    };
    // A tap-row (skip entirely when hs<0 — tap is exact zero; empty commit keeps group math)
    auto stage_A = [&](int hs) {
        if (hs >= 0) {
            #pragma unroll 3
            for (int q = tid; q < 2304; q += 256) {
                int ci = q / 36, j = q - (q / 36) * 36;
                int wg = w0 + j*4 - 8;
                bool ok = (unsigned)wg < (unsigned)W;
                const float* src = rinT + ((long)(b*64 + ci)*H + hs)*W + (ok ? wg : 0);
                u32 z = ok ? 16u : 0u;
                CPA16Z(shb + (u32)(ci*SA + j*4)*4, src, z);
            }
        }
        CP_COMMIT();
    };
    auto stage_acts = [&](int ci0) {
        #pragma unroll 3
        for (int q = tid; q < 1280; q += 256) {
            int ci = q >> 5, j = q & 31;
            int wg = w0 + j*4;
            bool ok = wg < W;
            const float* src = g_cT + ((long)(b*CDT + ci0 + ci)*H + hm)*W + (ok ? wg : 0);
            u32 z = ok ? 16u : 0u;
            CPA16Z(shb + (u32)(ci*SC + j*4)*4, src, z);
        }
        CP_COMMIT();
    };
    auto slot = [&](int i) -> u32 { return (i & 1) ? BIGF : SMLF; };

    float acc[4][4][4];
    #pragma unroll
    for (int ms = 0; ms < 4; ms++)
        #pragma unroll
        for (int ns = 0; ns < 4; ns++)
            #pragma unroll
            for (int q = 0; q < 4; q++) acc[ms][ns][q] = 0.f;

    stage_A(h - 2*D);
    stage_w(SMLF, wA + 0*128, 1152, 64);

    // -------- 9 conv taps (row skipped when hs<0: zero contribution) --------
    for (int r = 0; r < 3; r++) {
        const int hs_r = h - (2 - r) * D;
        const bool live = (hs_r >= 0);
        #pragma unroll 1
        for (int kw = 0; kw < 3; kw++) {
            int i = 3*r + kw;
            if (i < 8)  stage_w(slot(i+1), wA + (i+1)*128, 1152, 64);
            else        stage_w(BIGF, wC, 128, 40);
            CP_WAIT1();
            __syncthreads();
            if (live) {
                const float* As = sh + (kw - 1)*D + 8;
                const float* Bs = sh + slot(i);
                #pragma unroll 2
                for (int kc = 0; kc < 8; kc++) gemm_k8(acc, As, SA, Bs, kc*8, pm, pn, gid, tg);
            }
            __syncthreads();
        }
        if (r < 2) stage_A(h - (1 - r)*D);
    }

    // -------- conditioner (K=80), two 40-row halves --------
    stage_acts(0);
    stage_w(SMLF, wC + 40*128, 128, 40);
    CP_WAIT1();
    __syncthreads();
    #pragma unroll 1
    for (int kc = 0; kc < 5; kc++) gemm_k8(acc, sh, SC, sh + BIGF, kc*8, pm, pn, gid, tg);
    __syncthreads();
    stage_acts(40);
    stage_w(BIGF, wU, 128, 64);
    CP_WAIT1();
    __syncthreads();
    #pragma unroll 1
    for (int kc = 5; kc < 10; kc++) gemm_k8(acc, sh, SC, sh + SMLF, kc*8 - 40, pm, pn, gid, tg);
    __syncthreads();

    // -------- scatter g [co][px], reset acc --------
    #pragma unroll
    for (int ms = 0; ms < 4; ms++)
        #pragma unroll
        for (int ns = 0; ns < 4; ns++) {
            int px0 = pm + ms*16 + gid, co0 = pn + ns*8 + tg*2;
            sh[co0*SC + px0]         = acc[ms][ns][0];
            sh[(co0+1)*SC + px0]     = acc[ms][ns][1];
            sh[co0*SC + px0 + 8]     = acc[ms][ns][2];
            sh[(co0+1)*SC + px0 + 8] = acc[ms][ns][3];
            acc[ms][ns][0] = acc[ms][ns][1] = acc[ms][ns][2] = acc[ms][ns][3] = 0.f;
        }
    __syncthreads();
    // gate (fast math): act = tanh(t)*sigmoid(s) = (1 - 2/(1+e^{2t})) / (1+e^{-s})
    for (int e = tid; e < 64*128; e += 256) {
        int ci = e >> 7, px = e & 127;
        float t = sh[ci*SC + px], s = sh[(ci + 64)*SC + px];
        float th = 1.f - __fdividef(2.f, 1.f + __expf(2.f*t));
        float sg = __fdividef(1.f, 1.f + __expf(-s));
        sh[ci*SC + px] = tf32r(th * sg);
    }
    CP_WAIT0();
    __syncthreads();

    // -------- update GEMM --------
    #pragma unroll 2
    for (int kc = 0; kc < 8; kc++) gemm_k8(acc, sh, SC, sh + BIGF, kc*8, pm, pn, gid, tg);
    __syncthreads();
    float* d2 = sh + SMLF;
    #pragma unroll
    for (int ms = 0; ms < 4; ms++)
        #pragma unroll
        for (int ns = 0; ns < 4; ns++) {
            int px0 = pm + ms*16 + gid, co0 = pn + ns*8 + tg*2;
            d2[co0*SC + px0]         = acc[ms][ns][0];
            d2[(co0+1)*SC + px0]     = acc[ms][ns][1];
            d2[co0*SC + px0 + 8]     = acc[ms][ns][2];
            d2[(co0+1)*SC + px0 + 8] = acc[ms][ns][3];
        }
    __syncthreads();

    // writeout
    {
        int co = tid >> 1;
        int ph = (tid & 1) * 64;
        int ch = co & 63;
        long gb = ((long)(b*64 + ch)*H + h)*W + w0 + ph;
        const float4* dp = (const float4*)(d2 + co*SC + ph);
        if (co < 64) {
            #pragma unroll 4
            for (int j = 0; j < 16; j++) {
                if (w0 + ph + j*4 < W) {
                    float4 rv = *(const float4*)(rin + gb + j*4);
                    float4 dv = dp[j];
                    rv.x += dv.x; rv.y += dv.y; rv.z += dv.z; rv.w += dv.w;
                    *(float4*)(rout + gb + j*4) = rv;
                    float4 rt = make_float4(tf32r(rv.x), tf32r(rv.y), tf32r(rv.z), tf32r(rv.w));
                    *(float4*)(routT + gb + j*4) = rt;
                }
            }
        } else {
            #pragma unroll 4
            for (int j = 0; j < 16; j++) {
                if (w0 + ph + j*4 < W) {
                    float4 sv = *(const float4*)(g_skp + gb + j*4);
                    float4 dv = dp[j];
                    sv.x += dv.x; sv.y += dv.y; sv.z += dv.z; sv.w += dv.w;
                    *(float4*)(g_skp + gb + j*4) = sv;
                }
            }
        }
    }
}

// ---------------- post ----------------
__global__ void __launch_bounds__(256) post_kernel(const float* __restrict__ p1,
                                                   const float* __restrict__ p2,
                                                   const float* __restrict__ xext,
                                                   float* __restrict__ out, int flow)
{
    __shared__ float p1T[64*64];
    __shared__ float p2s[128];
    for (int i = threadIdx.x; i < 4096; i += 256) p1T[(i & 63)*64 + (i >> 6)] = p1[i];
    if (threadIdx.x < 128) p2s[threadIdx.x] = p2[threadIdx.x];
    __syncthreads();
    int pix = blockIdx.x * 256 + threadIdx.x;
    if (pix >= NPIX) return;
    int b = pix / PLANE, rem = pix - b * PLANE, h = rem / W, w = rem - (rem / W) * W;

    u64 h2[32];
    #pragma unroll
    for (int k = 0; k < 32; k++) h2[k] = 0ull;
    for (int j = 0; j < 64; j++) {
        float s = fmaxf(g_skp[((b*64 + j)*H + h)*W + w], 0.f);
        u64 ss = dup2(s);
        const ulonglong2* pr = (const ulonglong2*)(p1T + j*64);
        #pragma unroll
        for (int k2 = 0; k2 < 16; k2++) {
            ulonglong2 wv2 = pr[k2];
            ffma2(h2[2*k2], wv2.x, ss);
            ffma2(h2[2*k2+1], wv2.y, ss);
        }
    }
    float o0 = 0.f, o1 = 0.f;
    #pragma unroll
    for (int k = 0; k < 32; k++) {
        float lo, hi; unpk(h2[k], lo, hi);
        float a = fmaxf(lo, 0.f), bb = fmaxf(hi, 0.f);
        o0 = fmaf(p2s[2*k], a, o0);      o0 = fmaf(p2s[2*k+1], bb, o0);
        o1 = fmaf(p2s[64+2*k], a, o1);   o1 = fmaf(p2s[64+2*k+1], bb, o1);
    }
    float mean = o0, lv = fminf(o1, 10.f), e = expf(lv);
    float* gm = out + NPIX; float* gl = out + 2*NPIX;
    if (flow == 0) { gm[pix] = mean; gl[pix] = lv; }
    else           { gm[pix] = gm[pix]*e + mean; gl[pix] += lv; }
    const float* xs = (flow == 0) ? xext : g_xbuf[(flow + 1) & 1];
    float xn = e * xs[pix] + mean;
    int hd = (flow < 4) ? (15 - h) : (h < 8 ? 7 - h : 23 - h);
    int odx = b*PLANE + hd*W + w;
    g_xbuf[flow & 1][odx] = xn;
    if (flow == NFLOW - 1) out[odx] = xn;
}

// ---------------- host ----------------
extern "C" void kernel_launch(void* const* d_in, const int* in_sizes, int n_in,
                              void* d_out, int out_size)
{
    const float* x       = (const float*)d_in[0];
    const float* c       = (const float*)d_in[1];
    const float* first_w = (const float*)d_in[2];
    const float* init_w  = (const float*)d_in[3];
    const float* cdt_w   = (const float*)d_in[4];
    const float* res_w   = (const float*)d_in[5];
    const float* skp_w   = (const float*)d_in[6];
    const float* p1      = (const float*)d_in[7];
    const float* p2      = (const float*)d_in[8];
    float* out = (float*)d_out;

    const int SMEMB = SMEMF * 4;   // 108544 B -> 2 CTAs/SM
    cudaFuncSetAttribute(layer_kernel<1>, cudaFuncAttributeMaxDynamicSharedMemorySize, SMEMB);
    cudaFuncSetAttribute(layer_kernel<2>, cudaFuncAttributeMaxDynamicSharedMemorySize, SMEMB);
    cudaFuncSetAttribute(layer_kernel<4>, cudaFuncAttributeMaxDynamicSharedMemorySize, SMEMB);
    cudaFuncSetAttribute(layer_kernel<8>, cudaFuncAttributeMaxDynamicSharedMemorySize, SMEMB);

    long tot = (long)N1 + N2 + N3 + NC;
    prep_weights<<<(unsigned)((tot + 255) / 256), 256>>>(init_w, cdt_w, res_w, skp_w, c);

    dim3 gl((W + 127) / 128, B * H);   // (32, 32)
    for (int f = 0; f < NFLOW; f++) {
        first_conv<<<(NPIX + 255) / 256, 256>>>(first_w + f * 128, x, f);
        for (int l = 0; l < NLAYER; l++) {
            int d = 1 << (l & 3);
            int fl = f * NLAYER + l;
            int rb = l & 1;
            switch (d) {
                case 1:  layer_kernel<1><<<gl, 256, SMEMB>>>(f, fl, rb); break;
                case 2:  layer_kernel<2><<<gl, 256, SMEMB>>>(f, fl, rb); break;
                case 4:  layer_kernel<4><<<gl, 256, SMEMB>>>(f, fl, rb); break;
                default: layer_kernel<8><<<gl, 256, SMEMB>>>(f, fl, rb); break;
            }
        }
        post_kernel<<<(NPIX + 255) / 256, 256>>>(p1 + f * 64 * 64, p2 + f * 2 * 64, x, out, f);
    }
    (void)in_sizes; (void)n_in; (void)out_size;
}

// round 15
// speedup vs baseline: 2.7965x; 1.0484x over previous
#include <cuda_runtime.h>
#include <math.h>
#include <stdint.h>

#define B 2
#define H 16
#define W 4000
#define PLANE (H*W)
#define NPIX (B*PLANE)
#define CDT 80
#define NFLOW 8
#define NLAYER 8
typedef unsigned long long u64;
typedef unsigned int u32;

// smem layout (floats): [R1 9728][SML 8704][BIG 8704] = 27136 floats = 108544 B
#define SA 152
#define SB 136
#define SC 136
#define SMLF 9728
#define BIGF 18432
#define SMEMF 27136

// ---------------- helpers ----------------
__device__ __forceinline__ u32 smem_u32(const void* p) {
    u32 a; asm("{ .reg .u64 t; cvta.to.shared.u64 t, %1; cvt.u32.u64 %0, t; }" : "=r"(a) : "l"(p));
    return a;
}
__device__ __forceinline__ float tf32r(float x) {
    u32 r; asm("cvt.rna.tf32.f32 %0, %1;" : "=r"(r) : "f"(x));
    return __uint_as_float(r);
}
__device__ __forceinline__ u64 dup2(float x) { u64 r; asm("mov.b64 %0, {%1, %1};" : "=l"(r) : "f"(x)); return r; }
__device__ __forceinline__ void ffma2(u64& d, u64 a, u64 b) { asm("fma.rn.f32x2 %0, %1, %2, %0;" : "+l"(d) : "l"(a), "l"(b)); }
__device__ __forceinline__ void unpk(u64 v, float& lo, float& hi) { asm("mov.b64 {%0, %1}, %2;" : "=f"(lo), "=f"(hi) : "l"(v)); }

#define CPA16(d, s)     asm volatile("cp.async.cg.shared.global [%0], [%1], 16;" :: "r"(d), "l"(s) : "memory")
#define CPA16Z(d, s, z) asm volatile("cp.async.cg.shared.global [%0], [%1], 16, %2;" :: "r"(d), "l"(s), "r"(z) : "memory")
#define CP_COMMIT() asm volatile("cp.async.commit_group;" ::: "memory")
#define CP_WAIT1()  asm volatile("cp.async.wait_group 1;" ::: "memory")
#define CP_WAIT0()  asm volatile("cp.async.wait_group 0;" ::: "memory")

__device__ __forceinline__ void mma8(float* d, const u32* a, u32 b0, u32 b1) {
    asm("mma.sync.aligned.m16n8k8.row.col.f32.tf32.tf32.f32 "
        "{%0,%1,%2,%3}, {%4,%5,%6,%7}, {%8,%9}, {%0,%1,%2,%3};"
        : "+f"(d[0]), "+f"(d[1]), "+f"(d[2]), "+f"(d[3])
        : "r"(a[0]), "r"(a[1]), "r"(a[2]), "r"(a[3]), "r"(b0), "r"(b1));
}

__device__ __forceinline__ void gemm_k8(float (&acc)[4][4][4],
    const float* As, int sa, const float* Bs, int k0, int pm, int pn, int gid, int tg)
{
    u32 a[4][4];
    const float* ar = As + (k0 + tg) * sa;
    #pragma unroll
    for (int ms = 0; ms < 4; ms++) {
        const float* ap = ar + pm + ms*16 + gid;
        a[ms][0] = __float_as_uint(ap[0]);
        a[ms][1] = __float_as_uint(ap[8]);
        a[ms][2] = __float_as_uint(ap[4*sa]);
        a[ms][3] = __float_as_uint(ap[4*sa + 8]);
    }
    const float* br = Bs + (k0 + tg) * SB + pn + gid;
    #pragma unroll
    for (int ns = 0; ns < 4; ns++) {
        u32 b0 = __float_as_uint(br[ns*8]);
        u32 b1 = __float_as_uint(br[ns*8 + 4*SB]);
        #pragma unroll
        for (int ms = 0; ms < 4; ms++) mma8(acc[ms][ns], a[ms], b0, b1);
    }
}

// ---------------- persistent scratch ----------------
__device__ __align__(16) float g_res2[2][B*64*PLANE];
__device__ __align__(16) float g_resT[2][B*64*PLANE];
__device__ __align__(16) float g_skp[B*64*PLANE];
__device__ __align__(16) float g_xbuf[2][NPIX];
__device__ __align__(16) float g_cT [B*CDT*PLANE];
__device__ __align__(16) float g_wT [NFLOW*NLAYER*64*9*128];
__device__ __align__(16) float g_cwT[NFLOW*NLAYER*CDT*128];
__device__ __align__(16) float g_uwT[NFLOW*NLAYER*64*128];

#define N1 (NFLOW*NLAYER*64*9*128)
#define N2 (NFLOW*NLAYER*CDT*128)
#define N3 (NFLOW*NLAYER*64*128)
#define NC (B*CDT*PLANE)

// g-column interleave: tanh ci -> 2ci, sigmoid ci -> 2ci+1 (pairs land in one thread's c-frag)
__device__ __forceinline__ int gperm(int co) { return (co < 64) ? 2*co : 2*(co - 64) + 1; }

__global__ void prep_weights(const float* __restrict__ iw, const float* __restrict__ cw,
                             const float* __restrict__ rw, const float* __restrict__ sw,
                             const float* __restrict__ cfull)
{
    long idx = (long)blockIdx.x * 256 + threadIdx.x;
    if (idx < N1) {
        int co  = (int)(idx & 127);
        long t  = idx >> 7;
        int tap = (int)(t % 9); t /= 9;
        int ci  = (int)(t & 63);
        int fl  = (int)(t >> 6);
        int kh = tap / 3, kw = tap % 3;
        // dst column permuted (write idx base with gperm(co))
        long base = idx - co;
        g_wT[base + gperm(co)] = tf32r(iw[((((long)fl*128 + co)*64 + ci)*3 + kh)*3 + kw]);
    } else if (idx < N1 + N2) {
        long i2 = idx - N1;
        int co = (int)(i2 & 127);
        long t = i2 >> 7;
        int ci = (int)(t % CDT);
        int fl = (int)(t / CDT);
        long base = i2 - co;
        g_cwT[base + gperm(co)] = tf32r(cw[((long)fl*128 + co)*CDT + ci]);
    } else if (idx < N1 + N2 + N3) {
        long i3 = idx - N1 - N2;
        int o  = (int)(i3 & 127);
        long t = i3 >> 7;
        int ci = (int)(t & 63);
        int fl = (int)(t >> 6);
        g_uwT[i3] = tf32r((o < 64) ? rw[((long)fl*64 + o)*64 + ci]
                                   : sw[((long)fl*64 + (o-64))*64 + ci]);
    } else if (idx < N1 + N2 + N3 + NC) {
        long i4 = idx - N1 - N2 - N3;
        g_cT[i4] = tf32r(cfull[i4]);
    }
}

// ---------------- first conv ----------------
__global__ void __launch_bounds__(256) first_conv(const float* __restrict__ fw,
                                                  const float* __restrict__ xext, int flow)
{
    __shared__ float fsh[128];
    if (threadIdx.x < 128) fsh[threadIdx.x] = fw[threadIdx.x];
    __syncthreads();
    int pix = blockIdx.x * 256 + threadIdx.x;
    if (pix >= NPIX) return;
    int b = pix / PLANE, rem = pix - b * PLANE, h = rem / W, w = rem - (rem / W) * W;
    const float* xs = (flow == 0) ? xext : g_xbuf[(flow + 1) & 1];
    float x2 = (h >= 2) ? xs[pix - 2*W] : 0.f;
    float x1 = (h >= 1) ? xs[pix - W]   : 0.f;
    #pragma unroll 4
    for (int o = 0; o < 64; o++) {
        float v = tanhf(fsh[2*o]*x2 + fsh[2*o+1]*x1);
        int idx = ((b*64 + o)*H + h)*W + w;
        g_res2[0][idx] = v;
        g_resT[0][idx] = tf32r(v);
        g_skp[idx] = 0.f;
    }
}

// ---------------- fused layer: warp-MMA tf32, gate-in-registers ----------------
template<int D>
__global__ void __launch_bounds__(256, 2) layer_kernel(int flow, int fl, int rb)
{
    extern __shared__ __align__(16) float sh[];
    const int tid = threadIdx.x, lane = tid & 31, wq = tid >> 5;
    const int b = blockIdx.y >> 4, h = blockIdx.y & 15;
    const int w0 = blockIdx.x * 128;
    const int pm = (wq & 1) * 64, pn = (wq >> 1) * 32;
    const int gid = lane >> 2, tg = lane & 3;
    const float* rin  = g_res2[rb];
    const float* rinT = g_resT[rb];
    float* rout  = g_res2[rb ^ 1];
    float* routT = g_resT[rb ^ 1];
    const u32 shb = smem_u32(sh);

    const float* wA = g_wT + (long)fl*73728;
    const float* wC = g_cwT + (long)fl*10240;
    const float* wU = g_uwT + (long)fl*8192;

    int hm = h;
    #pragma unroll 1
    for (int j = flow - 1; j >= 0; j--)
        hm = (j < 4) ? (15 - hm) : (hm < 8 ? 7 - hm : 23 - hm);

    auto stage_w = [&](u32 dst_off, const float* src, int sstr, int rows) {
        u32 dstb = shb + dst_off * 4;
        int nq = rows * 32;
        for (int q = tid; q < nq; q += 256) {
            int ci = q >> 5, jj = q & 31;
            CPA16(dstb + (u32)(ci*SB + jj*4)*4, src + (long)ci*sstr + jj*4);
        }
        CP_COMMIT();
    };
    auto stage_A = [&](int hs) {
        if (hs >= 0) {
            #pragma unroll 3
            for (int q = tid; q < 2304; q += 256) {
                int ci = q / 36, j = q - (q / 36) * 36;
                int wg = w0 + j*4 - 8;
                bool ok = (unsigned)wg < (unsigned)W;
                const float* src = rinT + ((long)(b*64 + ci)*H + hs)*W + (ok ? wg : 0);
                u32 z = ok ? 16u : 0u;
                CPA16Z(shb + (u32)(ci*SA + j*4)*4, src, z);
            }
        }
        CP_COMMIT();
    };
    auto stage_acts = [&](int ci0) {
        #pragma unroll 3
        for (int q = tid; q < 1280; q += 256) {
            int ci = q >> 5, j = q & 31;
            int wg = w0 + j*4;
            bool ok = wg < W;
            const float* src = g_cT + ((long)(b*CDT + ci0 + ci)*H + hm)*W + (ok ? wg : 0);
            u32 z = ok ? 16u : 0u;
            CPA16Z(shb + (u32)(ci*SC + j*4)*4, src, z);
        }
        CP_COMMIT();
    };
    auto slot = [&](int i) -> u32 { return (i & 1) ? BIGF : SMLF; };

    float acc[4][4][4];
    #pragma unroll
    for (int ms = 0; ms < 4; ms++)
        #pragma unroll
        for (int ns = 0; ns < 4; ns++)
            #pragma unroll
            for (int q = 0; q < 4; q++) acc[ms][ns][q] = 0.f;

    stage_A(h - 2*D);
    stage_w(SMLF, wA + 0*128, 1152, 64);

    // -------- 9 conv taps (row skipped when hs<0) --------
    for (int r = 0; r < 3; r++) {
        const bool live = (h - (2 - r) * D) >= 0;
        #pragma unroll 1
        for (int kw = 0; kw < 3; kw++) {
            int i = 3*r + kw;
            if (i < 8)  stage_w(slot(i+1), wA + (i+1)*128, 1152, 64);
            else        stage_w(BIGF, wC, 128, 40);
            CP_WAIT1();
            __syncthreads();
            if (live) {
                const float* As = sh + (kw - 1)*D + 8;
                const float* Bs = sh + slot(i);
                #pragma unroll 2
                for (int kc = 0; kc < 8; kc++) gemm_k8(acc, As, SA, Bs, kc*8, pm, pn, gid, tg);
            }
            __syncthreads();
        }
        if (r < 2) stage_A(h - (1 - r)*D);
    }

    // -------- conditioner (K=80), two 40-row halves --------
    stage_acts(0);
    stage_w(SMLF, wC + 40*128, 128, 40);
    CP_WAIT1();
    __syncthreads();
    #pragma unroll 1
    for (int kc = 0; kc < 5; kc++) gemm_k8(acc, sh, SC, sh + BIGF, kc*8, pm, pn, gid, tg);
    __syncthreads();
    stage_acts(40);
    stage_w(BIGF, wU, 128, 64);
    CP_WAIT1();
    __syncthreads();
    #pragma unroll 1
    for (int kc = 5; kc < 10; kc++) gemm_k8(acc, sh, SC, sh + SMLF, kc*8 - 40, pm, pn, gid, tg);
    __syncthreads();

    // -------- gate in registers: c-frags hold (tanh, sigmoid) pairs --------
    // thread (ns,tg): pair p = pn/2 + ns*4 + tg; act -> sh[p][px]
    #pragma unroll
    for (int ms = 0; ms < 4; ms++)
        #pragma unroll
        for (int ns = 0; ns < 4; ns++) {
            int px0 = pm + ms*16 + gid;
            int p   = (pn >> 1) + ns*4 + tg;
            float t0 = acc[ms][ns][0], s0 = acc[ms][ns][1];
            float t1 = acc[ms][ns][2], s1 = acc[ms][ns][3];
            float v0 = (1.f - __fdividef(2.f, 1.f + __expf(2.f*t0))) *
                       __fdividef(1.f, 1.f + __expf(-s0));
            float v1 = (1.f - __fdividef(2.f, 1.f + __expf(2.f*t1))) *
                       __fdividef(1.f, 1.f + __expf(-s1));
            sh[p*SC + px0]     = tf32r(v0);
            sh[p*SC + px0 + 8] = tf32r(v1);
            acc[ms][ns][0] = acc[ms][ns][1] = acc[ms][ns][2] = acc[ms][ns][3] = 0.f;
        }
    CP_WAIT0();                              // update weights arrived
    __syncthreads();

    // -------- update GEMM: D2[px][o] = act @ [rw|sw] --------
    #pragma unroll 2
    for (int kc = 0; kc < 8; kc++) gemm_k8(acc, sh, SC, sh + BIGF, kc*8, pm, pn, gid, tg);
    __syncthreads();
    float* d2 = sh + SMLF;
    #pragma unroll
    for (int ms = 0; ms < 4; ms++)
        #pragma unroll
        for (int ns = 0; ns < 4; ns++) {
            int px0 = pm + ms*16 + gid, co0 = pn + ns*8 + tg*2;
            d2[co0*SC + px0]         = acc[ms][ns][0];
            d2[(co0+1)*SC + px0]     = acc[ms][ns][1];
            d2[co0*SC + px0 + 8]     = acc[ms][ns][2];
            d2[(co0+1)*SC + px0 + 8] = acc[ms][ns][3];
        }
    __syncthreads();

    // writeout
    {
        int co = tid >> 1;
        int ph = (tid & 1) * 64;
        int ch = co & 63;
        long gb = ((long)(b*64 + ch)*H + h)*W + w0 + ph;
        const float4* dp = (const float4*)(d2 + co*SC + ph);
        if (co < 64) {
            #pragma unroll 4
            for (int j = 0; j < 16; j++) {
                if (w0 + ph + j*4 < W) {
                    float4 rv = *(const float4*)(rin + gb + j*4);
                    float4 dv = dp[j];
                    rv.x += dv.x; rv.y += dv.y; rv.z += dv.z; rv.w += dv.w;
                    *(float4*)(rout + gb + j*4) = rv;
                    float4 rt = make_float4(tf32r(rv.x), tf32r(rv.y), tf32r(rv.z), tf32r(rv.w));
                    *(float4*)(routT + gb + j*4) = rt;
                }
            }
        } else {
            #pragma unroll 4
            for (int j = 0; j < 16; j++) {
                if (w0 + ph + j*4 < W) {
                    float4 sv = *(const float4*)(g_skp + gb + j*4);
                    float4 dv = dp[j];
                    sv.x += dv.x; sv.y += dv.y; sv.z += dv.z; sv.w += dv.w;
                    *(float4*)(g_skp + gb + j*4) = sv;
                }
            }
        }
    }
}

// ---------------- post ----------------
__global__ void __launch_bounds__(256) post_kernel(const float* __restrict__ p1,
                                                   const float* __restrict__ p2,
                                                   const float* __restrict__ xext,
                                                   float* __restrict__ out, int flow)
{
    __shared__ float p1T[64*64];
    __shared__ float p2s[128];
    for (int i = threadIdx.x; i < 4096; i += 256) p1T[(i & 63)*64 + (i >> 6)] = p1[i];
    if (threadIdx.x < 128) p2s[threadIdx.x] = p2[threadIdx.x];
    __syncthreads();
    int pix = blockIdx.x * 256 + threadIdx.x;
    if (pix >= NPIX) return;
    int b = pix / PLANE, rem = pix - b * PLANE, h = rem / W, w = rem - (rem / W) * W;

    u64 h2[32];
    #pragma unroll
    for (int k = 0; k < 32; k++) h2[k] = 0ull;
    for (int j = 0; j < 64; j++) {
        float s = fmaxf(g_skp[((b*64 + j)*H + h)*W + w], 0.f);
        u64 ss = dup2(s);
        const ulonglong2* pr = (const ulonglong2*)(p1T + j*64);
        #pragma unroll
        for (int k2 = 0; k2 < 16; k2++) {
            ulonglong2 wv2 = pr[k2];
            ffma2(h2[2*k2], wv2.x, ss);
            ffma2(h2[2*k2+1], wv2.y, ss);
        }
    }
    float o0 = 0.f, o1 = 0.f;
    #pragma unroll
    for (int k = 0; k < 32; k++) {
        float lo, hi; unpk(h2[k], lo, hi);
        float a = fmaxf(lo, 0.f), bb = fmaxf(hi, 0.f);
        o0 = fmaf(p2s[2*k], a, o0);      o0 = fmaf(p2s[2*k+1], bb, o0);
        o1 = fmaf(p2s[64+2*k], a, o1);   o1 = fmaf(p2s[64+2*k+1], bb, o1);
    }
    float mean = o0, lv = fminf(o1, 10.f), e = expf(lv);
    float* gm = out + NPIX; float* gl = out + 2*NPIX;
    if (flow == 0) { gm[pix] = mean; gl[pix] = lv; }
    else           { gm[pix] = gm[pix]*e + mean; gl[pix] += lv; }
    const float* xs = (flow == 0) ? xext : g_xbuf[(flow + 1) & 1];
    float xn = e * xs[pix] + mean;
    int hd = (flow < 4) ? (15 - h) : (h < 8 ? 7 - h : 23 - h);
    int odx = b*PLANE + hd*W + w;
    g_xbuf[flow & 1][odx] = xn;
    if (flow == NFLOW - 1) out[odx] = xn;
}

// ---------------- host ----------------
extern "C" void kernel_launch(void* const* d_in, const int* in_sizes, int n_in,
                              void* d_out, int out_size)
{
    const float* x       = (const float*)d_in[0];
    const float* c       = (const float*)d_in[1];
    const float* first_w = (const float*)d_in[2];
    const float* init_w  = (const float*)d_in[3];
    const float* cdt_w   = (const float*)d_in[4];
    const float* res_w   = (const float*)d_in[5];
    const float* skp_w   = (const float*)d_in[6];
    const float* p1      = (const float*)d_in[7];
    const float* p2      = (const float*)d_in[8];
    float* out = (float*)d_out;

    const int SMEMB = SMEMF * 4;   // 108544 B -> 2 CTAs/SM
    cudaFuncSetAttribute(layer_kernel<1>, cudaFuncAttributeMaxDynamicSharedMemorySize, SMEMB);
    cudaFuncSetAttribute(layer_kernel<2>, cudaFuncAttributeMaxDynamicSharedMemorySize, SMEMB);
    cudaFuncSetAttribute(layer_kernel<4>, cudaFuncAttributeMaxDynamicSharedMemorySize, SMEMB);
    cudaFuncSetAttribute(layer_kernel<8>, cudaFuncAttributeMaxDynamicSharedMemorySize, SMEMB);

    long tot = (long)N1 + N2 + N3 + NC;
    prep_weights<<<(unsigned)((tot + 255) / 256), 256>>>(init_w, cdt_w, res_w, skp_w, c);

    dim3 gl((W + 127) / 128, B * H);   // (32, 32)
    for (int f = 0; f < NFLOW; f++) {
        first_conv<<<(NPIX + 255) / 256, 256>>>(first_w + f * 128, x, f);
        for (int l = 0; l < NLAYER; l++) {
            int d = 1 << (l & 3);
            int fl = f * NLAYER + l;
            int rb = l & 1;
            switch (d) {
                case 1:  layer_kernel<1><<<gl, 256, SMEMB>>>(f, fl, rb); break;
                case 2:  layer_kernel<2><<<gl, 256, SMEMB>>>(f, fl, rb); break;
                case 4:  layer_kernel<4><<<gl, 256, SMEMB>>>(f, fl, rb); break;
                default: layer_kernel<8><<<gl, 256, SMEMB>>>(f, fl, rb); break;
            }
        }
        post_kernel<<<(NPIX + 255) / 256, 256>>>(p1 + f * 64 * 64, p2 + f * 2 * 64, x, out, f);
    }
    (void)in_sizes; (void)n_in; (void)out_size;
}